// round 3
// baseline (speedup 1.0000x reference)
#include <cuda_runtime.h>

#define BB 8
#define SS 16
#define TT 128
#define DD 64
#define NN 2048              // SS*TT
#define NEGV (-1000000000.0f)

// scratch (12 MB total) — device globals per harness rules
__device__ float g_q [BB*NN*DD];
__device__ float g_k [BB*NN*DD];
__device__ float g_vp[BB*NN*DD];   // V pre-permuted: row (t*SS + s)

// ---------------- kernel 1: QKV projection (64 rows / CTA) ----------------
// out[r][c] = sum_kk x[r][kk] * W[c][kk] + b[c]
__global__ void __launch_bounds__(256)
qkv_kernel(const float* __restrict__ x,
           const float* __restrict__ Wq_w, const float* __restrict__ Wq_b,
           const float* __restrict__ Wk_w, const float* __restrict__ Wk_b,
           const float* __restrict__ Wv_w, const float* __restrict__ Wv_b)
{
    extern __shared__ float sm1[];
    float* xs = sm1;               // [64][68]  (pad 68: row stride ≡ 4 mod 32)
    float* wt = xs + 64*68;        // [3][64][68]  wt[m][kk][c] = W[c][kk]
    float* bs = wt + 3*64*68;      // [3][64]

    int tid = threadIdx.x;
    int r0  = blockIdx.x * 64;

    for (int idx = tid; idx < 64*64; idx += 256) {
        int c = idx >> 6, kk = idx & 63;
        wt[(0*64 + kk)*68 + c] = Wq_w[idx];
        wt[(1*64 + kk)*68 + c] = Wk_w[idx];
        wt[(2*64 + kk)*68 + c] = Wv_w[idx];
    }
    if (tid < 64) {
        bs[tid]       = Wq_b[tid];
        bs[64 + tid]  = Wk_b[tid];
        bs[128 + tid] = Wv_b[tid];
    }
    #pragma unroll
    for (int it = 0; it < 4; it++) {
        int idx = tid + (it << 8);        // float4 index 0..1023
        int r = idx >> 4, f = idx & 15;
        float4 v = *(const float4*)(x + (size_t)(r0 + r)*64 + (f << 2));
        *(float4*)&xs[r*68 + (f << 2)] = v;
    }
    __syncthreads();

    int cg   = tid & 7;        // cols 8cg .. 8cg+7
    int rg   = tid >> 3;       // rows 2rg, 2rg+1
    int row0 = rg << 1;
    const float* x0p = &xs[row0 * 68];
    const float* x1p = x0p + 68;

    for (int mat = 0; mat < 3; mat++) {
        float a00,a01,a02,a03,a04,a05,a06,a07;
        float a10,a11,a12,a13,a14,a15,a16,a17;
        {
            const float* bp = &bs[mat*64 + 8*cg];
            a00=bp[0]; a01=bp[1]; a02=bp[2]; a03=bp[3];
            a04=bp[4]; a05=bp[5]; a06=bp[6]; a07=bp[7];
            a10=bp[0]; a11=bp[1]; a12=bp[2]; a13=bp[3];
            a14=bp[4]; a15=bp[5]; a16=bp[6]; a17=bp[7];
        }
        const float* wp = &wt[mat*64*68 + 8*cg];
        #pragma unroll 8
        for (int kk = 0; kk < 64; kk++) {
            float q0 = x0p[kk], q1 = x1p[kk];
            float4 w0 = *(const float4*)(wp + kk*68);
            float4 w1 = *(const float4*)(wp + kk*68 + 4);
            a00 += q0*w0.x; a01 += q0*w0.y; a02 += q0*w0.z; a03 += q0*w0.w;
            a04 += q0*w1.x; a05 += q0*w1.y; a06 += q0*w1.z; a07 += q0*w1.w;
            a10 += q1*w0.x; a11 += q1*w0.y; a12 += q1*w0.z; a13 += q1*w0.w;
            a14 += q1*w1.x; a15 += q1*w1.y; a16 += q1*w1.z; a17 += q1*w1.w;
        }
        float* dst = (mat == 0) ? g_q : (mat == 1) ? g_k : g_vp;
        // row rr=0
        {
            int gr = r0 + row0;
            int orow = gr;
            if (mat == 2) {
                int b_ = gr >> 11; int n = gr & 2047;
                int s_ = n >> 7;   int t_ = n & 127;
                orow = (b_ << 11) + (t_ << 4) + s_;
            }
            float* o = dst + (size_t)orow*64 + 8*cg;
            *(float4*)o     = make_float4(a00,a01,a02,a03);
            *(float4*)(o+4) = make_float4(a04,a05,a06,a07);
        }
        // row rr=1
        {
            int gr = r0 + row0 + 1;
            int orow = gr;
            if (mat == 2) {
                int b_ = gr >> 11; int n = gr & 2047;
                int s_ = n >> 7;   int t_ = n & 127;
                orow = (b_ << 11) + (t_ << 4) + s_;
            }
            float* o = dst + (size_t)orow*64 + 8*cg;
            *(float4*)o     = make_float4(a10,a11,a12,a13);
            *(float4*)(o+4) = make_float4(a14,a15,a16,a17);
        }
    }
}

// ---------------- kernel 2: attention, one CTA = (batch, 16-row tile) ----------------
__global__ void __launch_bounds__(256)
attn_kernel(const int* __restrict__ tags, const float* __restrict__ mask,
            float* __restrict__ ctx, float* __restrict__ p)
{
    extern __shared__ float sm2[];
    float* sc   = sm2;                 // [16][2048] scores, then exp values
    float* qs   = sc + 16*2048;        // [16][64]
    float* ms   = qs + 16*64;          // [16][128] base mask rows
    float* kv   = ms + 16*128;         // 8192 floats: kst[64][128] (xor-swizzled) / vsm[128][64]
    float* red  = kv + 8192;           // [256]
    float* rmax = red + 256;           // [16]
    float* rinv = rmax + 16;           // [16]
    int*   tg   = (int*)(rinv + 16);   // [16]
    int*   uni  = tg + 16;             // [17] (16 flags + anyUniform)

    int tid  = threadIdx.x;
    int b    = blockIdx.y;
    int tile = blockIdx.x;
    int n0   = tile << 4;              // first row (within batch)
    int s    = n0 >> 7;                // all 16 rows share one s
    int t0   = n0 & 127;

    if (tid < 16) tg[tid] = tags[(b << 4) + tid];
    {
        int r = tid >> 4, f = tid & 15;
        *(float4*)&qs[r*64 + (f << 2)] =
            *(const float4*)(g_q + (size_t)((b << 11) + n0 + r)*64 + (f << 2));
    }
    #pragma unroll
    for (int it = 0; it < 2; it++) {
        int idx = tid + (it << 8);
        int r = idx >> 5, f = idx & 31;
        *(float4*)&ms[r*128 + (f << 2)] =
            *(const float4*)(mask + (size_t)(t0 + r)*128 + (f << 2));
    }
    __syncthreads();

    int mytag = tg[s];
    unsigned vmask = 0;
    #pragma unroll
    for (int s2 = 0; s2 < 16; s2++) if (tg[s2] == mytag) vmask |= 1u << s2;

    // ---- scores: per valid 128-col block ----
    {
        int cg = tid & 63;                 // cols {cg, cg+64}
        int rq = (tid >> 6) << 2;          // rows rq .. rq+3
        const float* q0 = &qs[rq * 64];
        for (int s2 = 0; s2 < 16; s2++) {
            if (!((vmask >> s2) & 1)) continue;   // uniform branch
            int m0 = s2 << 7;
            const float* kbase = g_k + (size_t)((b << 11) + m0)*64;
            // stage K transposed with xor-swizzle: kst[kk][m ^ (kk&31)] = K[m][kk]
            for (int idx = tid; idx < 8192; idx += 256) {
                int m = idx >> 6, f = idx & 63;
                kv[f*128 + (m ^ (f & 31))] = kbase[m*64 + f];
            }
            __syncthreads();
            float a00=0,a01=0,a10=0,a11=0,a20=0,a21=0,a30=0,a31=0;
            #pragma unroll 4
            for (int kk = 0; kk < 64; kk++) {
                int ci = cg ^ (kk & 31);
                float k0 = kv[kk*128 + ci];
                float k1 = kv[kk*128 + ci + 64];   // (cg+64)^s == (cg^s)+64
                float q0v = q0[kk], q1v = q0[64+kk], q2v = q0[128+kk], q3v = q0[192+kk];
                a00 += q0v*k0; a01 += q0v*k1;
                a10 += q1v*k0; a11 += q1v*k1;
                a20 += q2v*k0; a21 += q2v*k1;
                a30 += q3v*k0; a31 += q3v*k1;
            }
            float av[4][2] = {{a00,a01},{a10,a11},{a20,a21},{a30,a31}};
            #pragma unroll
            for (int rr = 0; rr < 4; rr++) {
                int row = rq + rr;
                #pragma unroll
                for (int jj = 0; jj < 2; jj++) {
                    int c = cg + (jj << 6);
                    float sv = (ms[row*128 + c] != 0.f) ? av[rr][jj]*0.125f : NEGV;
                    sc[row*2048 + m0 + c] = sv;
                }
            }
            __syncthreads();
        }
    }

    int ri = tid >> 4, sub = tid & 15;
    // ---- row max ----
    {
        float mx = -3.4e38f;
        for (int s2 = 0; s2 < 16; s2++) {
            if (!((vmask >> s2) & 1)) continue;
            const float* sp = &sc[ri*2048 + (s2 << 7)];
            #pragma unroll
            for (int c = 0; c < 128; c += 16) mx = fmaxf(mx, sp[c + sub]);
        }
        red[tid] = mx;
    }
    __syncthreads();
    if (tid < 16) {
        float mx = red[tid*16];
        #pragma unroll
        for (int j = 1; j < 16; j++) mx = fmaxf(mx, red[tid*16 + j]);
        rmax[tid] = mx;
        uni[tid]  = (mx <= -1.0e8f) ? 1 : 0;   // all entries masked -> uniform softmax
    }
    __syncthreads();
    // ---- exp + sum (in place) ----
    {
        float mx = rmax[ri];
        int   uf = uni[ri];
        float sumv = 0.f;
        for (int s2 = 0; s2 < 16; s2++) {
            if (!((vmask >> s2) & 1)) continue;
            float* sp = &sc[ri*2048 + (s2 << 7)];
            #pragma unroll
            for (int c = 0; c < 128; c += 16) {
                float svv = sp[c + sub];
                float e = uf ? 1.f : ((svv > -1.0e8f) ? __expf(svv - mx) : 0.f);
                sp[c + sub] = e;
                sumv += e;
            }
        }
        red[tid] = sumv;
    }
    __syncthreads();
    if (tid < 16) {
        float sv = 0.f;
        #pragma unroll
        for (int j = 0; j < 16; j++) sv += red[tid*16 + j];
        rinv[tid] = uni[tid] ? (1.f/2048.f) : 1.f/sv;
    }
    if (tid == 0) {
        int a = 0;
        #pragma unroll
        for (int j = 0; j < 16; j++) a |= uni[j];
        uni[16] = a;
    }
    __syncthreads();
    int anyU = uni[16];

    // ---- write p_attn (normalized; zeros for masked blocks) ----
    {
        float4* pb = (float4*)(p + (size_t)((b << 11) + n0)*2048);
        for (int i = 0; i < 16; i++) {
            float inv = rinv[i];
            int   uf  = uni[i];
            const float* sp = &sc[i*2048];
            float4* prow = pb + (size_t)i*512;
            #pragma unroll
            for (int it = 0; it < 2; it++) {
                int f4 = tid + (it << 8);
                int c  = f4 << 2;
                float4 v;
                if (uf) { v.x = v.y = v.z = v.w = inv; }
                else if ((vmask >> (c >> 7)) & 1u) {
                    float4 e = *(const float4*)(sp + c);
                    v.x = e.x*inv; v.y = e.y*inv; v.z = e.z*inv; v.w = e.w*inv;
                } else { v.x = v.y = v.z = v.w = 0.f; }
                prow[f4] = v;
            }
        }
    }
    __syncthreads();

    // ---- AV: ctx[i][:] = inv * sum_m e[i][m] * vperm[m][:] ----
    {
        int dq = tid & 15;
        int i  = tid >> 4;
        float4 acc = make_float4(0.f, 0.f, 0.f, 0.f);
        const float4* gvb = (const float4*)(g_vp + (size_t)(b << 11)*64);
        float4* kvf = (float4*)kv;
        for (int s2 = 0; s2 < 16; s2++) {
            int vbit = (vmask >> s2) & 1;
            if (!vbit && !anyU) continue;          // uniform branch
            int m0 = s2 << 7;
            #pragma unroll
            for (int it = 0; it < 8; it++) {
                int idx = tid + (it << 8);
                kvf[idx] = gvb[(size_t)(m0 << 4) + idx];
            }
            __syncthreads();
            if (vbit) {
                const float* ep = &sc[i*2048 + m0];
                #pragma unroll 8
                for (int m = 0; m < 128; m++) {
                    float e = ep[m];
                    float4 vv = kvf[(m << 4) + dq];
                    acc.x += e*vv.x; acc.y += e*vv.y; acc.z += e*vv.z; acc.w += e*vv.w;
                }
            } else if (uni[i]) {                   // unreachable with bench input, kept for fidelity
                for (int m = 0; m < 128; m++) {
                    float4 vv = kvf[(m << 4) + dq];
                    acc.x += vv.x; acc.y += vv.y; acc.z += vv.z; acc.w += vv.w;
                }
            }
            __syncthreads();
        }
        float inv = rinv[i];
        *(float4*)(ctx + (size_t)((b << 11) + n0 + i)*64 + (dq << 2)) =
            make_float4(acc.x*inv, acc.y*inv, acc.z*inv, acc.w*inv);
    }
}

#define SMEM1 ((64*68 + 3*64*68 + 3*64) * 4)                     // 70400 B
// floats: sc 32768 + qs 1024 + ms 2048 + kv 8192 + red 256 + rmax 16 + rinv 16 = 44320
// ints:   tg 16 + uni 17 = 33      -> (44320 + 33)*4 = 177412 B, pad to 177664
#define SMEM2 (((44320 + 33) * 4 + 255) & ~255)

extern "C" void kernel_launch(void* const* d_in, const int* in_sizes, int n_in,
                              void* d_out, int out_size) {
    const float* x    = (const float*)d_in[0];
    const int*   tags = (const int*)  d_in[1];
    const float* mk   = (const float*)d_in[2];
    const float* Wk_w = (const float*)d_in[3];
    const float* Wk_b = (const float*)d_in[4];
    const float* Wq_w = (const float*)d_in[5];
    const float* Wq_b = (const float*)d_in[6];
    const float* Wv_w = (const float*)d_in[7];
    const float* Wv_b = (const float*)d_in[8];

    float* ctx = (float*)d_out;                        // [8,16,128,64]
    float* p   = ctx + (size_t)BB*SS*TT*DD;            // [8,2048,2048]

    cudaFuncSetAttribute(qkv_kernel,  cudaFuncAttributeMaxDynamicSharedMemorySize, SMEM1);
    cudaFuncSetAttribute(attn_kernel, cudaFuncAttributeMaxDynamicSharedMemorySize, SMEM2);

    qkv_kernel<<<256, 256, SMEM1>>>(x, Wq_w, Wq_b, Wk_w, Wk_b, Wv_w, Wv_b);
    attn_kernel<<<dim3(NN/16, BB), 256, SMEM2>>>(tags, mk, ctx, p);
}

// round 4
// speedup vs baseline: 1.6771x; 1.6771x over previous
#include <cuda_runtime.h>

#define BB 8
#define SS 16
#define TT 128
#define DD 64
#define NN 2048              // SS*TT
#define NEGV (-1000000000.0f)
#define SCW 2052             // padded score-strip row stride (floats)

// scratch — device globals per harness rules
__device__ float g_q [BB*NN*DD];
__device__ float g_kT[BB*DD*NN];   // K transposed: [b][kk][n]
__device__ float g_vp[BB*NN*DD];   // V pre-permuted: row (t*SS + s)

typedef unsigned long long ull;

__device__ __forceinline__ ull pk2(float x, float y){
    ull r; asm("mov.b64 %0, {%1, %2};" : "=l"(r) : "f"(x), "f"(y)); return r;
}
__device__ __forceinline__ void fma2(ull &d, ull a, ull b){
    asm("fma.rn.f32x2 %0, %1, %2, %0;" : "+l"(d) : "l"(a), "l"(b));
}
__device__ __forceinline__ float2 upk2(ull v){
    float2 r; asm("mov.b64 {%0, %1}, %2;" : "=f"(r.x), "=f"(r.y) : "l"(v)); return r;
}

// ---------------- kernel 1: QKV projection (64 rows / CTA), FFMA2 ----------------
__global__ void __launch_bounds__(256)
qkv_kernel(const float* __restrict__ x,
           const float* __restrict__ Wq_w, const float* __restrict__ Wq_b,
           const float* __restrict__ Wk_w, const float* __restrict__ Wk_b,
           const float* __restrict__ Wv_w, const float* __restrict__ Wv_b)
{
    extern __shared__ float sm1[];
    float* xs = sm1;               // [64][68]
    float* wt = xs + 64*68;        // [3][64][68]  wt[m][kk][c] = W[c][kk]
    float* bs = wt + 3*64*68;      // [3][64]

    int tid = threadIdx.x;
    int r0  = blockIdx.x * 64;

    for (int idx = tid; idx < 64*64; idx += 256) {
        int c = idx >> 6, kk = idx & 63;
        wt[(0*64 + kk)*68 + c] = Wq_w[idx];
        wt[(1*64 + kk)*68 + c] = Wk_w[idx];
        wt[(2*64 + kk)*68 + c] = Wv_w[idx];
    }
    if (tid < 64) {
        bs[tid]       = Wq_b[tid];
        bs[64 + tid]  = Wk_b[tid];
        bs[128 + tid] = Wv_b[tid];
    }
    #pragma unroll
    for (int it = 0; it < 4; it++) {
        int idx = tid + (it << 8);
        int r = idx >> 4, f = idx & 15;
        float4 v = *(const float4*)(x + (size_t)(r0 + r)*64 + (f << 2));
        *(float4*)&xs[r*68 + (f << 2)] = v;
    }
    __syncthreads();

    int cg   = tid & 7;        // cols 8cg..8cg+7
    int rg   = tid >> 3;       // rows 2rg, 2rg+1
    int row0 = rg << 1;
    const float* x0p = &xs[row0 * 68];
    const float* x1p = x0p + 68;
    int gr0 = r0 + row0;
    int b_  = gr0 >> 11;
    int n_  = gr0 & 2047;

    for (int mat = 0; mat < 3; mat++) {
        ull a0[4], a1[4];
        {
            const ulonglong2* bp = (const ulonglong2*)(bs + mat*64 + 8*cg);
            ulonglong2 b01 = bp[0], b23 = bp[1];
            a0[0]=b01.x; a0[1]=b01.y; a0[2]=b23.x; a0[3]=b23.y;
            a1[0]=b01.x; a1[1]=b01.y; a1[2]=b23.x; a1[3]=b23.y;
        }
        const float* wp = &wt[mat*64*68 + 8*cg];
        #pragma unroll 4
        for (int kk = 0; kk < 64; kk++) {
            float q0 = x0p[kk], q1 = x1p[kk];
            ull q0p = pk2(q0, q0), q1p = pk2(q1, q1);
            ulonglong2 w01 = *(const ulonglong2*)(wp + kk*68);
            ulonglong2 w23 = *(const ulonglong2*)(wp + kk*68 + 4);
            fma2(a0[0], q0p, w01.x); fma2(a0[1], q0p, w01.y);
            fma2(a0[2], q0p, w23.x); fma2(a0[3], q0p, w23.y);
            fma2(a1[0], q1p, w01.x); fma2(a1[1], q1p, w01.y);
            fma2(a1[2], q1p, w23.x); fma2(a1[3], q1p, w23.y);
        }
        if (mat == 1) {
            // K: write transposed [b][col][n]
            #pragma unroll
            for (int p = 0; p < 4; p++) {
                float2 v0 = upk2(a0[p]);
                float2 v1 = upk2(a1[p]);
                int c = 8*cg + 2*p;
                g_kT[(size_t)((b_<<6) + c    )*2048 + n_    ] = v0.x;
                g_kT[(size_t)((b_<<6) + c + 1)*2048 + n_    ] = v0.y;
                g_kT[(size_t)((b_<<6) + c    )*2048 + n_ + 1] = v1.x;
                g_kT[(size_t)((b_<<6) + c + 1)*2048 + n_ + 1] = v1.y;
            }
        } else {
            float* dst = (mat == 0) ? g_q : g_vp;
            #pragma unroll
            for (int rr = 0; rr < 2; rr++) {
                int gr = gr0 + rr;
                int orow = gr;
                if (mat == 2) {
                    int bq = gr >> 11; int n = gr & 2047;
                    int s_ = n >> 7;   int t_ = n & 127;
                    orow = (bq << 11) + (t_ << 4) + s_;
                }
                ull* ap = rr ? a1 : a0;
                float2 u0 = upk2(ap[0]), u1 = upk2(ap[1]);
                float2 u2 = upk2(ap[2]), u3 = upk2(ap[3]);
                float* o = dst + (size_t)orow*64 + 8*cg;
                *(float4*)o     = make_float4(u0.x,u0.y,u1.x,u1.y);
                *(float4*)(o+4) = make_float4(u2.x,u2.y,u3.x,u3.y);
            }
        }
    }
}

// ---------------- kernel 2: attention ----------------
// smem float offsets
#define OF_SC   0
#define OF_KST  (16*SCW)                 // 32832
#define OF_QS   (OF_KST + 2*8192)        // 49216
#define OF_MS   (OF_QS + 1024)           // 50240
#define OF_RED  (OF_MS + 2048)           // 52288
#define OF_RMAX (OF_RED + 256)           // 52544
#define OF_RINV (OF_RMAX + 16)           // 52560
#define OF_TG   (OF_RINV + 16)           // 52576 (ints)
#define OF_UNI  (OF_TG + 16)             // 52592 (ints, 17)
#define OF_VL   (OF_UNI + 17)            // 52609 (ints, 16)
#define OF_NV   (OF_VL + 16)             // 52625 (int)
#define SMEM2_FLOATS (OF_NV + 1)         // 52626
#define SMEM2 (((SMEM2_FLOATS*4) + 127) & ~127)

__global__ void __launch_bounds__(256)
attn_kernel(const int* __restrict__ tags, const float* __restrict__ mask,
            float* __restrict__ ctx, float* __restrict__ p)
{
    extern __shared__ float sm2[];
    float* sc   = sm2 + OF_SC;          // [16][SCW]
    float* kst  = sm2 + OF_KST;         // 2 x [64][128]; reused as vsm[128][64] + pav[4][16][64]
    float* qs   = sm2 + OF_QS;          // [16][64]
    float* ms   = sm2 + OF_MS;          // [16][128]
    float* red  = sm2 + OF_RED;         // [256]
    float* rmax = sm2 + OF_RMAX;
    float* rinv = sm2 + OF_RINV;
    int*   tg   = (int*)(sm2 + OF_TG);
    int*   uni  = (int*)(sm2 + OF_UNI);
    int*   vl   = (int*)(sm2 + OF_VL);
    int*   nvs  = (int*)(sm2 + OF_NV);

    int tid  = threadIdx.x;
    int b    = blockIdx.y;
    int n0   = blockIdx.x << 4;
    int s    = n0 >> 7;
    int t0   = n0 & 127;

    if (tid < 16) tg[tid] = tags[(b << 4) + tid];
    {
        int r = tid >> 4, f = tid & 15;
        *(float4*)&qs[r*64 + (f << 2)] =
            *(const float4*)(g_q + (size_t)((b << 11) + n0 + r)*64 + (f << 2));
    }
    #pragma unroll
    for (int it = 0; it < 2; it++) {
        int idx = tid + (it << 8);
        int r = idx >> 5, f = idx & 31;
        *(float4*)&ms[r*128 + (f << 2)] =
            *(const float4*)(mask + (size_t)(t0 + r)*128 + (f << 2));
    }
    __syncthreads();

    int mytag = tg[s];
    unsigned vmask = 0;
    #pragma unroll
    for (int s2 = 0; s2 < 16; s2++) if (tg[s2] == mytag) vmask |= 1u << s2;
    if (tid == 0) {
        int nvt = 0;
        #pragma unroll
        for (int s2 = 0; s2 < 16; s2++) if ((vmask >> s2) & 1) vl[nvt++] = s2;
        nvs[0] = nvt;
    }
    __syncthreads();
    int nv = nvs[0];

    // ---- scores: 2 K-blocks concurrently, 4x4 register tiles, FFMA2 ----
    {
        int half = tid >> 7;
        int lt   = tid & 127;
        int cq   = lt & 31;
        int rgs  = lt >> 5;
        int r0s  = rgs << 2;
        for (int pi = 0; pi < nv; pi += 2) {
            int nblk = (nv - pi < 2) ? (nv - pi) : 2;
            for (int bi = 0; bi < nblk; bi++) {
                int m0 = vl[pi + bi] << 7;
                float* dstb = kst + bi*8192;
                #pragma unroll
                for (int it = 0; it < 8; it++) {
                    int idx = tid + (it << 8);
                    int kk = idx >> 5, qm = idx & 31;
                    *(float4*)(dstb + kk*128 + (qm << 2)) =
                        *(const float4*)(g_kT + (size_t)((b << 6) + kk)*2048 + m0 + (qm << 2));
                }
            }
            __syncthreads();
            if (half < nblk) {
                const float* kbl = kst + half*8192;
                int m0 = vl[pi + half] << 7;
                ull a[4][2];
                #pragma unroll
                for (int rr = 0; rr < 4; rr++) { a[rr][0] = 0ull; a[rr][1] = 0ull; }
                const float* q0p = qs + r0s*64;
                #pragma unroll 4
                for (int kk = 0; kk < 64; kk++) {
                    ulonglong2 kp = *(const ulonglong2*)(kbl + kk*128 + (cq << 2));
                    float qa = q0p[kk], qb = q0p[64+kk], qc = q0p[128+kk], qd = q0p[192+kk];
                    ull qap = pk2(qa,qa), qbp = pk2(qb,qb), qcp = pk2(qc,qc), qdp = pk2(qd,qd);
                    fma2(a[0][0], qap, kp.x); fma2(a[0][1], qap, kp.y);
                    fma2(a[1][0], qbp, kp.x); fma2(a[1][1], qbp, kp.y);
                    fma2(a[2][0], qcp, kp.x); fma2(a[2][1], qcp, kp.y);
                    fma2(a[3][0], qdp, kp.x); fma2(a[3][1], qdp, kp.y);
                }
                #pragma unroll
                for (int rr = 0; rr < 4; rr++) {
                    int row = r0s + rr;
                    float2 v0 = upk2(a[rr][0]), v1 = upk2(a[rr][1]);
                    float4 mr = *(const float4*)(ms + row*128 + (cq << 2));
                    float4 o;
                    o.x = (mr.x != 0.f) ? v0.x*0.125f : NEGV;
                    o.y = (mr.y != 0.f) ? v0.y*0.125f : NEGV;
                    o.z = (mr.z != 0.f) ? v1.x*0.125f : NEGV;
                    o.w = (mr.w != 0.f) ? v1.y*0.125f : NEGV;
                    *(float4*)(sc + row*SCW + m0 + (cq << 2)) = o;
                }
            }
            __syncthreads();
        }
    }

    int ri = tid >> 4, sub = tid & 15;
    // ---- row max ----
    {
        float mx = -3.4e38f;
        for (int vi = 0; vi < nv; vi++) {
            const float* sp = &sc[ri*SCW + (vl[vi] << 7)];
            #pragma unroll
            for (int c = 0; c < 128; c += 16) mx = fmaxf(mx, sp[c + sub]);
        }
        red[tid] = mx;
    }
    __syncthreads();
    if (tid < 16) {
        float mx = red[tid*16];
        #pragma unroll
        for (int j = 1; j < 16; j++) mx = fmaxf(mx, red[tid*16 + j]);
        rmax[tid] = mx;
        uni[tid]  = (mx <= -1.0e8f) ? 1 : 0;
    }
    __syncthreads();
    // ---- exp + sum (in place) ----
    {
        float mx = rmax[ri];
        int   uf = uni[ri];
        float sumv = 0.f;
        for (int vi = 0; vi < nv; vi++) {
            float* sp = &sc[ri*SCW + (vl[vi] << 7)];
            #pragma unroll
            for (int c = 0; c < 128; c += 16) {
                float svv = sp[c + sub];
                float e = uf ? 1.f : ((svv > -1.0e8f) ? __expf(svv - mx) : 0.f);
                sp[c + sub] = e;
                sumv += e;
            }
        }
        red[tid] = sumv;
    }
    __syncthreads();
    if (tid < 16) {
        float sv = 0.f;
        #pragma unroll
        for (int j = 0; j < 16; j++) sv += red[tid*16 + j];
        rinv[tid] = uni[tid] ? (1.f/2048.f) : 1.f/sv;
    }
    if (tid == 0) {
        int a = 0;
        #pragma unroll
        for (int j = 0; j < 16; j++) a |= uni[j];
        uni[16] = a;
    }
    __syncthreads();
    int anyU = uni[16];

    // ---- write p_attn ----
    {
        float4* pb = (float4*)(p + (size_t)((b << 11) + n0)*2048);
        for (int i = 0; i < 16; i++) {
            float inv = rinv[i];
            int   uf  = uni[i];
            const float* sp = sc + i*SCW;
            float4* prow = pb + (size_t)i*512;
            #pragma unroll
            for (int it = 0; it < 2; it++) {
                int f4 = tid + (it << 8);
                int c  = f4 << 2;
                float4 v;
                if (uf) { v.x = v.y = v.z = v.w = inv; }
                else if ((vmask >> (c >> 7)) & 1u) {
                    float4 e = *(const float4*)(sp + c);
                    v.x = e.x*inv; v.y = e.y*inv; v.z = e.z*inv; v.w = e.w*inv;
                } else { v.x = v.y = v.z = v.w = 0.f; }
                prow[f4] = v;
            }
        }
    }

    // ---- AV: register-tiled, m-split 4, FFMA2 ----
    {
        float* vsm = kst;                 // [128][64]
        float* pav = kst + 8192;          // [4][16][64]
        int dq  = tid & 15;
        int rg2 = (tid >> 4) & 3;
        int msl = tid >> 6;
        int r0a = rg2 << 2;
        int u0 = 0, u1 = 0, u2 = 0, u3 = 0;
        if (anyU) { u0 = uni[r0a]; u1 = uni[r0a+1]; u2 = uni[r0a+2]; u3 = uni[r0a+3]; }
        ull acc[4][2];
        #pragma unroll
        for (int rr = 0; rr < 4; rr++) { acc[rr][0] = 0ull; acc[rr][1] = 0ull; }
        const float4* gvb = (const float4*)(g_vp + (size_t)(b << 11)*64);
        float4* vf4 = (float4*)vsm;

        for (int s2 = 0; s2 < 16; s2++) {
            int vbit = (vmask >> s2) & 1;
            if (!vbit && !anyU) continue;
            int m0 = s2 << 7;
            __syncthreads();
            #pragma unroll
            for (int it = 0; it < 8; it++) {
                int idx = tid + (it << 8);
                vf4[idx] = gvb[(size_t)(m0 << 4) + idx];
            }
            __syncthreads();
            if (vbit) {
                const float* e0 = sc + (r0a    )*SCW + m0 + (msl << 5);
                const float* e1 = sc + (r0a + 1)*SCW + m0 + (msl << 5);
                const float* e2 = sc + (r0a + 2)*SCW + m0 + (msl << 5);
                const float* e3 = sc + (r0a + 3)*SCW + m0 + (msl << 5);
                const float* vb = vsm + (msl << 5)*64 + (dq << 2);
                #pragma unroll 4
                for (int mm = 0; mm < 32; mm++) {
                    ulonglong2 vp = *(const ulonglong2*)(vb + mm*64);
                    float ea = e0[mm], eb = e1[mm], ec = e2[mm], ed = e3[mm];
                    ull eap = pk2(ea,ea), ebp = pk2(eb,eb), ecp = pk2(ec,ec), edp = pk2(ed,ed);
                    fma2(acc[0][0], eap, vp.x); fma2(acc[0][1], eap, vp.y);
                    fma2(acc[1][0], ebp, vp.x); fma2(acc[1][1], ebp, vp.y);
                    fma2(acc[2][0], ecp, vp.x); fma2(acc[2][1], ecp, vp.y);
                    fma2(acc[3][0], edp, vp.x); fma2(acc[3][1], edp, vp.y);
                }
            } else {
                // invalid block, uniform rows accumulate V with weight 1
                const float* vb = vsm + (msl << 5)*64 + (dq << 2);
                ull one = pk2(1.f, 1.f);
                for (int mm = 0; mm < 32; mm++) {
                    ulonglong2 vp = *(const ulonglong2*)(vb + mm*64);
                    if (u0) { fma2(acc[0][0], one, vp.x); fma2(acc[0][1], one, vp.y); }
                    if (u1) { fma2(acc[1][0], one, vp.x); fma2(acc[1][1], one, vp.y); }
                    if (u2) { fma2(acc[2][0], one, vp.x); fma2(acc[2][1], one, vp.y); }
                    if (u3) { fma2(acc[3][0], one, vp.x); fma2(acc[3][1], one, vp.y); }
                }
            }
        }
        __syncthreads();
        #pragma unroll
        for (int rr = 0; rr < 4; rr++) {
            float2 w0 = upk2(acc[rr][0]), w1 = upk2(acc[rr][1]);
            *(float4*)(pav + ((msl*16 + r0a + rr)*64) + (dq << 2)) =
                make_float4(w0.x, w0.y, w1.x, w1.y);
        }
        __syncthreads();
        {
            int row = tid >> 4, d4 = tid & 15;
            float4 s0 = *(float4*)(pav + ((0*16 + row)*64) + (d4 << 2));
            float4 s1 = *(float4*)(pav + ((1*16 + row)*64) + (d4 << 2));
            float4 s2v = *(float4*)(pav + ((2*16 + row)*64) + (d4 << 2));
            float4 s3 = *(float4*)(pav + ((3*16 + row)*64) + (d4 << 2));
            float inv = rinv[row];
            float4 o;
            o.x = (s0.x + s1.x + s2v.x + s3.x) * inv;
            o.y = (s0.y + s1.y + s2v.y + s3.y) * inv;
            o.z = (s0.z + s1.z + s2v.z + s3.z) * inv;
            o.w = (s0.w + s1.w + s2v.w + s3.w) * inv;
            *(float4*)(ctx + (size_t)((b << 11) + n0 + row)*64 + (d4 << 2)) = o;
        }
    }
}

#define SMEM1 ((64*68 + 3*64*68 + 3*64) * 4)

extern "C" void kernel_launch(void* const* d_in, const int* in_sizes, int n_in,
                              void* d_out, int out_size) {
    const float* x    = (const float*)d_in[0];
    const int*   tags = (const int*)  d_in[1];
    const float* mk   = (const float*)d_in[2];
    const float* Wk_w = (const float*)d_in[3];
    const float* Wk_b = (const float*)d_in[4];
    const float* Wq_w = (const float*)d_in[5];
    const float* Wq_b = (const float*)d_in[6];
    const float* Wv_w = (const float*)d_in[7];
    const float* Wv_b = (const float*)d_in[8];

    float* ctx = (float*)d_out;                        // [8,16,128,64]
    float* p   = ctx + (size_t)BB*SS*TT*DD;            // [8,2048,2048]

    cudaFuncSetAttribute(qkv_kernel,  cudaFuncAttributeMaxDynamicSharedMemorySize, SMEM1);
    cudaFuncSetAttribute(attn_kernel, cudaFuncAttributeMaxDynamicSharedMemorySize, SMEM2);

    qkv_kernel<<<256, 256, SMEM1>>>(x, Wq_w, Wq_b, Wk_w, Wk_b, Wv_w, Wv_b);
    attn_kernel<<<dim3(NN/16, BB), 256, SMEM2>>>(tags, mk, ctx, p);
}

// round 5
// speedup vs baseline: 1.7062x; 1.0174x over previous
#include <cuda_runtime.h>

#define BB 8
#define SS 16
#define TT 128
#define DD 64
#define NN 2048              // SS*TT
#define NEGV (-1000000000.0f)
#define SCW 2052             // padded score-strip row stride (floats)

// scratch — device globals per harness rules
__device__ float g_q [BB*NN*DD];
__device__ float g_kT[BB*DD*NN];   // K transposed: [b][kk][n]
__device__ float g_vp[BB*NN*DD];   // V pre-permuted: row (t*SS + s)

typedef unsigned long long ull;

__device__ __forceinline__ ull pk2(float x, float y){
    ull r; asm("mov.b64 %0, {%1, %2};" : "=l"(r) : "f"(x), "f"(y)); return r;
}
__device__ __forceinline__ void fma2(ull &d, ull a, ull b){
    asm("fma.rn.f32x2 %0, %1, %2, %0;" : "+l"(d) : "l"(a), "l"(b));
}
__device__ __forceinline__ float2 upk2(ull v){
    float2 r; asm("mov.b64 {%0, %1}, %2;" : "=f"(r.x), "=f"(r.y) : "l"(v)); return r;
}

// ---------------- kernel 1: QKV projection (64 rows / CTA), FFMA2 ----------------
__global__ void __launch_bounds__(256)
qkv_kernel(const float* __restrict__ x,
           const float* __restrict__ Wq_w, const float* __restrict__ Wq_b,
           const float* __restrict__ Wk_w, const float* __restrict__ Wk_b,
           const float* __restrict__ Wv_w, const float* __restrict__ Wv_b)
{
    extern __shared__ float sm1[];
    float* xs = sm1;               // [64][68]
    float* wt = xs + 64*68;        // [3][64][68]  wt[m][kk][c] = W[c][kk]
    float* bs = wt + 3*64*68;      // [3][64]

    int tid = threadIdx.x;
    int r0  = blockIdx.x * 64;

    for (int idx = tid; idx < 64*64; idx += 256) {
        int c = idx >> 6, kk = idx & 63;
        wt[(0*64 + kk)*68 + c] = Wq_w[idx];
        wt[(1*64 + kk)*68 + c] = Wk_w[idx];
        wt[(2*64 + kk)*68 + c] = Wv_w[idx];
    }
    if (tid < 64) {
        bs[tid]       = Wq_b[tid];
        bs[64 + tid]  = Wk_b[tid];
        bs[128 + tid] = Wv_b[tid];
    }
    #pragma unroll
    for (int it = 0; it < 4; it++) {
        int idx = tid + (it << 8);
        int r = idx >> 4, f = idx & 15;
        float4 v = *(const float4*)(x + (size_t)(r0 + r)*64 + (f << 2));
        *(float4*)&xs[r*68 + (f << 2)] = v;
    }
    __syncthreads();

    int cg   = tid & 7;
    int rg   = tid >> 3;
    int row0 = rg << 1;
    const float* x0p = &xs[row0 * 68];
    const float* x1p = x0p + 68;
    int gr0 = r0 + row0;
    int b_  = gr0 >> 11;
    int n_  = gr0 & 2047;

    for (int mat = 0; mat < 3; mat++) {
        ull a0[4], a1[4];
        {
            const ulonglong2* bp = (const ulonglong2*)(bs + mat*64 + 8*cg);
            ulonglong2 b01 = bp[0], b23 = bp[1];
            a0[0]=b01.x; a0[1]=b01.y; a0[2]=b23.x; a0[3]=b23.y;
            a1[0]=b01.x; a1[1]=b01.y; a1[2]=b23.x; a1[3]=b23.y;
        }
        const float* wp = &wt[mat*64*68 + 8*cg];
        #pragma unroll 4
        for (int kk = 0; kk < 64; kk++) {
            float q0 = x0p[kk], q1 = x1p[kk];
            ull q0p = pk2(q0, q0), q1p = pk2(q1, q1);
            ulonglong2 w01 = *(const ulonglong2*)(wp + kk*68);
            ulonglong2 w23 = *(const ulonglong2*)(wp + kk*68 + 4);
            fma2(a0[0], q0p, w01.x); fma2(a0[1], q0p, w01.y);
            fma2(a0[2], q0p, w23.x); fma2(a0[3], q0p, w23.y);
            fma2(a1[0], q1p, w01.x); fma2(a1[1], q1p, w01.y);
            fma2(a1[2], q1p, w23.x); fma2(a1[3], q1p, w23.y);
        }
        if (mat == 1) {
            #pragma unroll
            for (int p = 0; p < 4; p++) {
                float2 v0 = upk2(a0[p]);
                float2 v1 = upk2(a1[p]);
                int c = 8*cg + 2*p;
                g_kT[(size_t)((b_<<6) + c    )*2048 + n_    ] = v0.x;
                g_kT[(size_t)((b_<<6) + c + 1)*2048 + n_    ] = v0.y;
                g_kT[(size_t)((b_<<6) + c    )*2048 + n_ + 1] = v1.x;
                g_kT[(size_t)((b_<<6) + c + 1)*2048 + n_ + 1] = v1.y;
            }
        } else {
            float* dst = (mat == 0) ? g_q : g_vp;
            #pragma unroll
            for (int rr = 0; rr < 2; rr++) {
                int gr = gr0 + rr;
                int orow = gr;
                if (mat == 2) {
                    int bq = gr >> 11; int n = gr & 2047;
                    int s_ = n >> 7;   int t_ = n & 127;
                    orow = (bq << 11) + (t_ << 4) + s_;
                }
                ull* ap = rr ? a1 : a0;
                float2 u0 = upk2(ap[0]), u1 = upk2(ap[1]);
                float2 u2 = upk2(ap[2]), u3 = upk2(ap[3]);
                float* o = dst + (size_t)orow*64 + 8*cg;
                *(float4*)o     = make_float4(u0.x,u0.y,u1.x,u1.y);
                *(float4*)(o+4) = make_float4(u2.x,u2.y,u3.x,u3.y);
            }
        }
    }
}

// ---------------- kernel 2: attention, 512 threads/CTA ----------------
// smem float offsets
#define OF_KST  (16*SCW)                 // 32832, size 16384 (2 K-blocks; reused: vsm 8192 + pav 8192)
#define OF_QD   (OF_KST + 16384)         // 49216, size 2048 ([64][16] float2 dup)
#define OF_MS   (OF_QD + 2048)           // 51264, size 2048
#define OF_RED  (OF_MS + 2048)           // 53312, size 512
#define OF_RMAX (OF_RED + 512)           // 53824
#define OF_RINV (OF_RMAX + 16)           // 53840
#define OF_TG   (OF_RINV + 16)           // 53856 (ints)
#define OF_UNI  (OF_TG + 16)             // 53872 (ints, 17)
#define OF_VL   (OF_UNI + 17)            // 53889 (ints, 16)
#define OF_NV   (OF_VL + 16)             // 53905 (int)
#define SMEM2_FLOATS (OF_NV + 1)
#define SMEM2 (((SMEM2_FLOATS*4) + 127) & ~127)

__global__ void __launch_bounds__(512)
attn_kernel(const int* __restrict__ tags, const float* __restrict__ mask,
            float* __restrict__ ctx, float* __restrict__ p)
{
    extern __shared__ float sm2[];
    float* sc   = sm2;                  // [16][SCW]
    float* kst  = sm2 + OF_KST;
    float* qd   = sm2 + OF_QD;          // [64][32] duplicated q
    float* ms   = sm2 + OF_MS;          // [16][128]
    float* red  = sm2 + OF_RED;         // [512]
    float* rmax = sm2 + OF_RMAX;
    float* rinv = sm2 + OF_RINV;
    int*   tg   = (int*)(sm2 + OF_TG);
    int*   uni  = (int*)(sm2 + OF_UNI);
    int*   vl   = (int*)(sm2 + OF_VL);
    int*   nvs  = (int*)(sm2 + OF_NV);

    int tid  = threadIdx.x;
    int b    = blockIdx.y;
    int n0   = blockIdx.x << 4;
    int s    = n0 >> 7;
    int t0   = n0 & 127;

    if (tid < 16) tg[tid] = tags[(b << 4) + tid];
    {   // mask: 512 float4 covers all 16x128
        int r = tid >> 5, f = tid & 31;
        *(float4*)&ms[r*128 + (f << 2)] =
            *(const float4*)(mask + (size_t)(t0 + r)*128 + (f << 2));
    }
    // build duplicated q: qd[kk][row] = {q,q}
    for (int i = tid; i < 1024; i += 512) {
        int kk = i >> 4, r = i & 15;
        float v = g_q[(size_t)((b << 11) + n0 + r)*64 + kk];
        qd[kk*32 + 2*r]     = v;
        qd[kk*32 + 2*r + 1] = v;
    }
    __syncthreads();

    int mytag = tg[s];
    unsigned vmask = 0;
    #pragma unroll
    for (int s2 = 0; s2 < 16; s2++) if (tg[s2] == mytag) vmask |= 1u << s2;
    if (tid == 0) {
        int nvt = 0;
        #pragma unroll
        for (int s2 = 0; s2 < 16; s2++) if ((vmask >> s2) & 1) vl[nvt++] = s2;
        nvs[0] = nvt;
    }
    __syncthreads();
    int nv = nvs[0];

    // ---- scores: 2 K-blocks x 256 threads; lane tile = 2 rows x 4 cols ----
    {
        int half = tid >> 8;
        int t    = tid & 255;
        int cq   = (t & 7) + (((t >> 5) & 3) << 3);   // 0..31 (warp: 8 distinct)
        int rp   = ((t >> 3) & 3) + (((t >> 7) & 1) << 2); // 0..7 (warp: 4 distinct)
        for (int pi = 0; pi < nv; pi += 2) {
            int nblk = (nv - pi < 2) ? (nv - pi) : 2;
            for (int bi = 0; bi < nblk; bi++) {
                int m0 = vl[pi + bi] << 7;
                float* dstb = kst + bi*8192;
                #pragma unroll
                for (int it = 0; it < 4; it++) {
                    int idx = tid + (it << 9);
                    int kk = idx >> 5, qm = idx & 31;
                    *(float4*)(dstb + kk*128 + (qm << 2)) =
                        *(const float4*)(g_kT + (size_t)((b << 6) + kk)*2048 + m0 + (qm << 2));
                }
            }
            __syncthreads();
            if (half < nblk) {
                const float* kbl = kst + half*8192;
                int m0 = vl[pi + half] << 7;
                ull a00 = 0, a01 = 0, a10 = 0, a11 = 0;
                #pragma unroll 8
                for (int kk = 0; kk < 64; kk++) {
                    ulonglong2 kp = *(const ulonglong2*)(kbl + kk*128 + (cq << 2));
                    ulonglong2 qp = *(const ulonglong2*)(qd + kk*32 + (rp << 2));
                    fma2(a00, qp.x, kp.x); fma2(a01, qp.x, kp.y);
                    fma2(a10, qp.y, kp.x); fma2(a11, qp.y, kp.y);
                }
                int row0 = rp << 1;
                float2 v00 = upk2(a00), v01 = upk2(a01);
                float2 v10 = upk2(a10), v11 = upk2(a11);
                float4 m0r = *(const float4*)(ms + row0*128 + (cq << 2));
                float4 m1r = *(const float4*)(ms + (row0+1)*128 + (cq << 2));
                float4 o0, o1;
                o0.x = (m0r.x != 0.f) ? v00.x*0.125f : NEGV;
                o0.y = (m0r.y != 0.f) ? v00.y*0.125f : NEGV;
                o0.z = (m0r.z != 0.f) ? v01.x*0.125f : NEGV;
                o0.w = (m0r.w != 0.f) ? v01.y*0.125f : NEGV;
                o1.x = (m1r.x != 0.f) ? v10.x*0.125f : NEGV;
                o1.y = (m1r.y != 0.f) ? v10.y*0.125f : NEGV;
                o1.z = (m1r.z != 0.f) ? v11.x*0.125f : NEGV;
                o1.w = (m1r.w != 0.f) ? v11.y*0.125f : NEGV;
                *(float4*)(sc + row0*SCW + m0 + (cq << 2))     = o0;
                *(float4*)(sc + (row0+1)*SCW + m0 + (cq << 2)) = o1;
            }
            __syncthreads();
        }
    }

    int ri = tid >> 5, sub = tid & 31;
    // ---- row max ----
    {
        float mx = -3.4e38f;
        for (int vi = 0; vi < nv; vi++) {
            const float* sp = &sc[ri*SCW + (vl[vi] << 7)];
            #pragma unroll
            for (int c = 0; c < 128; c += 32) mx = fmaxf(mx, sp[c + sub]);
        }
        red[tid] = mx;
    }
    __syncthreads();
    if (tid < 16) {
        float mx = red[tid*32];
        #pragma unroll
        for (int j = 1; j < 32; j++) mx = fmaxf(mx, red[tid*32 + j]);
        rmax[tid] = mx;
        uni[tid]  = (mx <= -1.0e8f) ? 1 : 0;
    }
    __syncthreads();
    // ---- exp + sum (in place) ----
    {
        float mx = rmax[ri];
        int   uf = uni[ri];
        float sumv = 0.f;
        for (int vi = 0; vi < nv; vi++) {
            float* sp = &sc[ri*SCW + (vl[vi] << 7)];
            #pragma unroll
            for (int c = 0; c < 128; c += 32) {
                float svv = sp[c + sub];
                float e = uf ? 1.f : ((svv > -1.0e8f) ? __expf(svv - mx) : 0.f);
                sp[c + sub] = e;
                sumv += e;
            }
        }
        red[tid] = sumv;
    }
    __syncthreads();
    if (tid < 16) {
        float sv = 0.f;
        #pragma unroll
        for (int j = 0; j < 32; j++) sv += red[tid*32 + j];
        rinv[tid] = uni[tid] ? (1.f/2048.f) : 1.f/sv;
    }
    if (tid == 0) {
        int a = 0;
        #pragma unroll
        for (int j = 0; j < 16; j++) a |= uni[j];
        uni[16] = a;
    }
    __syncthreads();
    int anyU = uni[16];

    // ---- write p_attn ----
    {
        float4* pb = (float4*)(p + (size_t)((b << 11) + n0)*2048);
        int c = tid << 2;
        int vb = (vmask >> (c >> 7)) & 1u;
        for (int i = 0; i < 16; i++) {
            float inv = rinv[i];
            int   uf  = uni[i];
            const float* sp = sc + i*SCW;
            float4 v;
            if (uf) { v.x = v.y = v.z = v.w = inv; }
            else if (vb) {
                float4 e = *(const float4*)(sp + c);
                v.x = e.x*inv; v.y = e.y*inv; v.z = e.z*inv; v.w = e.w*inv;
            } else { v.x = v.y = v.z = v.w = 0.f; }
            pb[(size_t)i*512 + tid] = v;
        }
    }

    // ---- AV: lane tile 4 rows x 4 cols, m-split 8 ----
    {
        float* vsm = kst;                 // [128][64]
        float* pav = kst + 8192;          // [8][16][64] -> wait: 8192 floats = 8*16*64 = 8192 ✓
        int cg  = tid & 15;               // 4 cols: 4cg
        int rg  = (tid >> 4) & 3;         // rows 4rg..4rg+3
        int msl = tid >> 6;               // 0..7 (m chunk of 16)
        int r0a = rg << 2;
        int u0 = 0, u1 = 0, u2 = 0, u3 = 0;
        if (anyU) { u0 = uni[r0a]; u1 = uni[r0a+1]; u2 = uni[r0a+2]; u3 = uni[r0a+3]; }
        ull acc[4][2];
        #pragma unroll
        for (int rr = 0; rr < 4; rr++) { acc[rr][0] = 0ull; acc[rr][1] = 0ull; }
        const float4* gvb = (const float4*)(g_vp + (size_t)(b << 11)*64);
        float4* vf4 = (float4*)vsm;

        for (int s2 = 0; s2 < 16; s2++) {
            int vbit = (vmask >> s2) & 1;
            if (!vbit && !anyU) continue;
            int m0 = s2 << 7;
            __syncthreads();
            #pragma unroll
            for (int it = 0; it < 4; it++) {
                int idx = tid + (it << 9);
                vf4[idx] = gvb[(size_t)(m0 << 4) + idx];
            }
            __syncthreads();
            if (vbit) {
                const float* e0 = sc + (r0a    )*SCW + m0 + (msl << 4);
                const float* e1 = e0 + SCW;
                const float* e2 = e1 + SCW;
                const float* e3 = e2 + SCW;
                const float* vb = vsm + (msl << 4)*64 + (cg << 2);
                #pragma unroll 4
                for (int mm = 0; mm < 16; mm++) {
                    ulonglong2 vp = *(const ulonglong2*)(vb + mm*64);
                    float ea = e0[mm], eb = e1[mm], ec = e2[mm], ed = e3[mm];
                    ull eap = pk2(ea,ea), ebp = pk2(eb,eb), ecp = pk2(ec,ec), edp = pk2(ed,ed);
                    fma2(acc[0][0], eap, vp.x); fma2(acc[0][1], eap, vp.y);
                    fma2(acc[1][0], ebp, vp.x); fma2(acc[1][1], ebp, vp.y);
                    fma2(acc[2][0], ecp, vp.x); fma2(acc[2][1], ecp, vp.y);
                    fma2(acc[3][0], edp, vp.x); fma2(acc[3][1], edp, vp.y);
                }
            } else {
                const float* vb = vsm + (msl << 4)*64 + (cg << 2);
                ull one = pk2(1.f, 1.f);
                for (int mm = 0; mm < 16; mm++) {
                    ulonglong2 vp = *(const ulonglong2*)(vb + mm*64);
                    if (u0) { fma2(acc[0][0], one, vp.x); fma2(acc[0][1], one, vp.y); }
                    if (u1) { fma2(acc[1][0], one, vp.x); fma2(acc[1][1], one, vp.y); }
                    if (u2) { fma2(acc[2][0], one, vp.x); fma2(acc[2][1], one, vp.y); }
                    if (u3) { fma2(acc[3][0], one, vp.x); fma2(acc[3][1], one, vp.y); }
                }
            }
        }
        __syncthreads();
        #pragma unroll
        for (int rr = 0; rr < 4; rr++) {
            float2 w0 = upk2(acc[rr][0]), w1 = upk2(acc[rr][1]);
            *(float4*)(pav + ((msl*16 + r0a + rr)*64) + (cg << 2)) =
                make_float4(w0.x, w0.y, w1.x, w1.y);
        }
        __syncthreads();
        {
            int row = tid >> 5, sb = tid & 31;
            if (sb < 16) {
                float4 o = make_float4(0.f, 0.f, 0.f, 0.f);
                #pragma unroll
                for (int m2 = 0; m2 < 8; m2++) {
                    float4 t4 = *(float4*)(pav + ((m2*16 + row)*64) + (sb << 2));
                    o.x += t4.x; o.y += t4.y; o.z += t4.z; o.w += t4.w;
                }
                float inv = rinv[row];
                o.x *= inv; o.y *= inv; o.z *= inv; o.w *= inv;
                *(float4*)(ctx + (size_t)((b << 11) + n0 + row)*64 + (sb << 2)) = o;
            }
        }
    }
}

#define SMEM1 ((64*68 + 3*64*68 + 3*64) * 4)

extern "C" void kernel_launch(void* const* d_in, const int* in_sizes, int n_in,
                              void* d_out, int out_size) {
    const float* x    = (const float*)d_in[0];
    const int*   tags = (const int*)  d_in[1];
    const float* mk   = (const float*)d_in[2];
    const float* Wk_w = (const float*)d_in[3];
    const float* Wk_b = (const float*)d_in[4];
    const float* Wq_w = (const float*)d_in[5];
    const float* Wq_b = (const float*)d_in[6];
    const float* Wv_w = (const float*)d_in[7];
    const float* Wv_b = (const float*)d_in[8];

    float* ctx = (float*)d_out;                        // [8,16,128,64]
    float* p   = ctx + (size_t)BB*SS*TT*DD;            // [8,2048,2048]

    cudaFuncSetAttribute(qkv_kernel,  cudaFuncAttributeMaxDynamicSharedMemorySize, SMEM1);
    cudaFuncSetAttribute(attn_kernel, cudaFuncAttributeMaxDynamicSharedMemorySize, SMEM2);

    qkv_kernel<<<256, 256, SMEM1>>>(x, Wq_w, Wq_b, Wk_w, Wk_b, Wv_w, Wv_b);
    attn_kernel<<<dim3(NN/16, BB), 512, SMEM2>>>(tags, mk, ctx, p);
}

// round 9
// speedup vs baseline: 2.7070x; 1.5865x over previous
#include <cuda_runtime.h>
#include <cuda_bf16.h>

#define BB 8
#define SS 16
#define TT 128
#define DD 64
#define NN 2048
#define NEGV (-1000000000.0f)
#define P0  (0.00048828125f)   // 1/2048, exact in bf16/fp32

typedef unsigned long long ull;
typedef unsigned int uint;

// bf16 split operands
__device__ __nv_bfloat16 g_qh[BB*NN*DD], g_ql[BB*NN*DD];
__device__ __nv_bfloat16 g_kh[BB*NN*DD], g_kl[BB*NN*DD];
__device__ __nv_bfloat16 g_vth[BB*DD*NN], g_vtl[BB*DD*NN]; // [b][d][mm] mm = t*16+s

__device__ __forceinline__ ull pk2(float x, float y){
    ull r; asm("mov.b64 %0, {%1, %2};" : "=l"(r) : "f"(x), "f"(y)); return r;
}
__device__ __forceinline__ void fma2(ull &d, ull a, ull b){
    asm("fma.rn.f32x2 %0, %1, %2, %0;" : "+l"(d) : "l"(a), "l"(b));
}
__device__ __forceinline__ float2 upk2(ull v){
    float2 r; asm("mov.b64 {%0, %1}, %2;" : "=f"(r.x), "=f"(r.y) : "l"(v)); return r;
}

// ---------------- kernel 1: QKV projection -> bf16 splits ----------------
__global__ void __launch_bounds__(256)
qkv_kernel(const float* __restrict__ x,
           const float* __restrict__ Wq_w, const float* __restrict__ Wq_b,
           const float* __restrict__ Wk_w, const float* __restrict__ Wk_b,
           const float* __restrict__ Wv_w, const float* __restrict__ Wv_b)
{
    extern __shared__ float sm1[];
    float* xs = sm1;               // [64][68]
    float* wt = xs + 64*68;        // [3][64][68]
    float* bs = wt + 3*64*68;      // [3][64]

    int tid = threadIdx.x;
    int r0  = blockIdx.x * 64;

    for (int idx = tid; idx < 64*64; idx += 256) {
        int c = idx >> 6, kk = idx & 63;
        wt[(0*64 + kk)*68 + c] = Wq_w[idx];
        wt[(1*64 + kk)*68 + c] = Wk_w[idx];
        wt[(2*64 + kk)*68 + c] = Wv_w[idx];
    }
    if (tid < 64) {
        bs[tid]       = Wq_b[tid];
        bs[64 + tid]  = Wk_b[tid];
        bs[128 + tid] = Wv_b[tid];
    }
    #pragma unroll
    for (int it = 0; it < 4; it++) {
        int idx = tid + (it << 8);
        int r = idx >> 4, f = idx & 15;
        float4 v = *(const float4*)(x + (size_t)(r0 + r)*64 + (f << 2));
        *(float4*)&xs[r*68 + (f << 2)] = v;
    }
    __syncthreads();

    int cg   = tid & 7;
    int rg   = tid >> 3;
    int row0 = rg << 1;
    const float* x0p = &xs[row0 * 68];
    const float* x1p = x0p + 68;
    int gr0 = r0 + row0;
    int b_  = gr0 >> 11;

    for (int mat = 0; mat < 3; mat++) {
        ull a0[4], a1[4];
        {
            const ulonglong2* bp = (const ulonglong2*)(bs + mat*64 + 8*cg);
            ulonglong2 b01 = bp[0], b23 = bp[1];
            a0[0]=b01.x; a0[1]=b01.y; a0[2]=b23.x; a0[3]=b23.y;
            a1[0]=b01.x; a1[1]=b01.y; a1[2]=b23.x; a1[3]=b23.y;
        }
        const float* wp = &wt[mat*64*68 + 8*cg];
        #pragma unroll 4
        for (int kk = 0; kk < 64; kk++) {
            float q0 = x0p[kk], q1 = x1p[kk];
            ull q0p = pk2(q0, q0), q1p = pk2(q1, q1);
            ulonglong2 w01 = *(const ulonglong2*)(wp + kk*68);
            ulonglong2 w23 = *(const ulonglong2*)(wp + kk*68 + 4);
            fma2(a0[0], q0p, w01.x); fma2(a0[1], q0p, w01.y);
            fma2(a0[2], q0p, w23.x); fma2(a0[3], q0p, w23.y);
            fma2(a1[0], q1p, w01.x); fma2(a1[1], q1p, w01.y);
            fma2(a1[2], q1p, w23.x); fma2(a1[3], q1p, w23.y);
        }
        #pragma unroll
        for (int rr = 0; rr < 2; rr++) {
            int gr = gr0 + rr;
            ull* ap = rr ? a1 : a0;
            float f[8];
            { float2 u0=upk2(ap[0]),u1=upk2(ap[1]),u2=upk2(ap[2]),u3=upk2(ap[3]);
              f[0]=u0.x; f[1]=u0.y; f[2]=u1.x; f[3]=u1.y;
              f[4]=u2.x; f[5]=u2.y; f[6]=u3.x; f[7]=u3.y; }
            __nv_bfloat16 h[8]; __nv_bfloat16 lo[8];
            #pragma unroll
            for (int i = 0; i < 8; i++) {
                h[i]  = __float2bfloat16(f[i]);
                lo[i] = __float2bfloat16(f[i] - __bfloat162float(h[i]));
            }
            if (mat < 2) {
                __nv_bfloat16* dh = (mat == 0) ? g_qh : g_kh;
                __nv_bfloat16* dl = (mat == 0) ? g_ql : g_kl;
                *(uint4*)(dh + (size_t)gr*64 + 8*cg) = *(uint4*)h;
                *(uint4*)(dl + (size_t)gr*64 + 8*cg) = *(uint4*)lo;
            } else {
                int n = gr & 2047;
                int s_ = n >> 7, t_ = n & 127;
                int mm = t_*16 + s_;
                size_t base = ((size_t)(b_*64 + 8*cg))*2048 + mm;
                #pragma unroll
                for (int i = 0; i < 8; i++) {
                    g_vth[base + (size_t)i*2048] = h[i];
                    g_vtl[base + (size_t)i*2048] = lo[i];
                }
            }
        }
    }
}

// ---------------- attention (mma.sync bf16-split) ----------------
#define OFF_QH 0
#define OFF_QL 16384
#define OFF_KH 32768
#define OFF_KL 49152
#define OFF_VH 65536
#define OFF_VL 81920
#define OFF_PH 98304
#define OFF_PL 131072
#define OFF_MSB  163840
#define OFF_STMP 165888
#define OFF_STLP 166912
#define OFF_UF   167936
#define OFF_FLAG 168448
#define OFF_TAGS 168452
#define SMEM_AT  168576

#define QOFF(r,c) ((uint)((r)*128 + (((c) ^ ((r)&7)) << 4)))
#define VOFF(r,c) ((uint)((r)*256 + (((c) ^ ((r)&7)) << 4)))

__device__ __forceinline__ uint smem_u32(const void* p){
    uint a; asm("{ .reg .u64 t; cvta.to.shared.u64 t, %1; cvt.u32.u64 %0, t; }" : "=r"(a) : "l"(p));
    return a;
}
__device__ __forceinline__ uint4 ldsm4(uint addr){
    uint4 r;
    asm volatile("ldmatrix.sync.aligned.m8n8.x4.shared.b16 {%0,%1,%2,%3}, [%4];"
        : "=r"(r.x), "=r"(r.y), "=r"(r.z), "=r"(r.w) : "r"(addr));
    return r;
}
__device__ __forceinline__ void mma16816(float* d, uint4 a, uint b0, uint b1){
    asm volatile("mma.sync.aligned.m16n8k16.row.col.f32.bf16.bf16.f32 "
        "{%0,%1,%2,%3}, {%4,%5,%6,%7}, {%8,%9}, {%0,%1,%2,%3};"
        : "+f"(d[0]), "+f"(d[1]), "+f"(d[2]), "+f"(d[3])
        : "r"(a.x), "r"(a.y), "r"(a.z), "r"(a.w), "r"(b0), "r"(b1));
}

__global__ void __launch_bounds__(512, 1)
attn_kernel(const int* __restrict__ tags, const float* __restrict__ mask,
            float* __restrict__ ctx, float* __restrict__ p)
{
    extern __shared__ char smem[];
    uint sb = smem_u32(smem);
    int tid  = threadIdx.x;
    int wid  = tid >> 5, lane = tid & 31;
    int wr   = wid >> 1;                 // row group 0..7
    int wh   = wid & 1;                  // col half
    int m0   = wr << 4;
    int nb   = wh << 6;                  // QK col base within block
    int db   = wh << 5;                  // AV d base
    int s    = blockIdx.x;
    int b    = blockIdx.y;
    int lq   = lane & 3;                 // col quad
    int lr   = lane >> 2;                // row within 8
    int rA   = m0 + lr, rB = rA + 8;

    int*   tgs  = (int*)(smem + OFF_TAGS);
    uint*  msb  = (uint*)(smem + OFF_MSB);
    float* stmp = (float*)(smem + OFF_STMP);
    float* stlp = (float*)(smem + OFF_STLP);
    int*   ufr  = (int*)(smem + OFF_UF);
    int*   flg  = (int*)(smem + OFF_FLAG);

    if (tid < 16) tgs[tid] = tags[b*16 + tid];
    if (tid == 0) flg[0] = 0;
    // mask bits
    for (int i = tid; i < 512; i += 512) {
        int tt = i >> 2, w = i & 3;
        uint bits = 0;
        #pragma unroll 8
        for (int j = 0; j < 32; j++)
            bits |= (mask[(size_t)tt*128 + w*32 + j] != 0.f ? 1u : 0u) << j;
        msb[i] = bits;
    }
    // stage Q
    #pragma unroll
    for (int it = 0; it < 2; it++) {
        int idx = tid + (it << 9);
        int r = idx >> 3, c = idx & 7;
        size_t se = ((size_t)((b << 11) + (s << 7) + r))*64 + c*8;
        *(uint4*)(smem + OFF_QH + QOFF(r, c)) = *(const uint4*)(g_qh + se);
        *(uint4*)(smem + OFF_QL + QOFF(r, c)) = *(const uint4*)(g_ql + se);
    }
    __syncthreads();

    int mytag = tgs[s];
    uint vmask = 0;
    #pragma unroll
    for (int s2 = 0; s2 < 16; s2++) if (tgs[s2] == mytag) vmask |= 1u << s2;
    int vlist[16], nv = 0;
    #pragma unroll
    for (int s2 = 0; s2 < 16; s2++) if ((vmask >> s2) & 1) vlist[nv++] = s2;

    // per-lane mask bits (16 cols per row)
    uint mbA = 0, mbB = 0;
    #pragma unroll
    for (int f = 0; f < 8; f++)
        #pragma unroll
        for (int u = 0; u < 2; u++) {
            int cw = nb + 8*f + 2*lq + u;
            mbA |= ((msb[rA*4 + (cw >> 5)] >> (cw & 31)) & 1u) << (f*2 + u);
            mbB |= ((msb[rB*4 + (cw >> 5)] >> (cw & 31)) & 1u) << (f*2 + u);
        }

    // ldmatrix lane addresses (fixed parts)
    int aRow = m0 + (lane & 7) + ((lane >> 3) & 1)*8;    // A (Q or P)
    int aChS = (lane >> 4);                              // + 2*ks
    int bRowOff = (lane & 7) + ((lane >= 16) ? 8 : 0);   // B row offset
    int bChS = ((lane >> 3) & 1);                        // + 2*ks

    float m_runA = -3.4e38f, l_runA = 0.f;
    float m_runB = -3.4e38f, l_runB = 0.f;

    // ================ pass 1: stats ================
    for (int vi = 0; vi < nv; vi++) {
        int s2 = vlist[vi];
        __syncthreads();
        #pragma unroll
        for (int it = 0; it < 2; it++) {
            int idx = tid + (it << 9);
            int r = idx >> 3, c = idx & 7;
            size_t se = ((size_t)((b << 11) + (s2 << 7) + r))*64 + c*8;
            *(uint4*)(smem + OFF_KH + QOFF(r, c)) = *(const uint4*)(g_kh + se);
            *(uint4*)(smem + OFF_KL + QOFF(r, c)) = *(const uint4*)(g_kl + se);
        }
        __syncthreads();
        float acc[8][4];
        #pragma unroll
        for (int f = 0; f < 8; f++) { acc[f][0]=0; acc[f][1]=0; acc[f][2]=0; acc[f][3]=0; }
        #pragma unroll
        for (int sp = 0; sp < 3; sp++) {
            uint qb = sb + ((sp == 2) ? OFF_QL : OFF_QH);
            uint kb = sb + ((sp == 1) ? OFF_KL : OFF_KH);
            #pragma unroll
            for (int ks = 0; ks < 4; ks++) {
                uint4 A = ldsm4(qb + QOFF(aRow, 2*ks + aChS));
                #pragma unroll
                for (int fp = 0; fp < 4; fp++) {
                    int n = nb + 16*fp;
                    uint4 Bv = ldsm4(kb + QOFF(n + bRowOff, 2*ks + bChS));
                    mma16816(acc[2*fp],     A, Bv.x, Bv.y);
                    mma16816(acc[2*fp + 1], A, Bv.z, Bv.w);
                }
            }
        }
        // mask + scale in place
        #pragma unroll
        for (int f = 0; f < 8; f++) {
            acc[f][0] = ((mbA >> (2*f)) & 1)   ? acc[f][0]*0.125f : NEGV;
            acc[f][1] = ((mbA >> (2*f+1)) & 1) ? acc[f][1]*0.125f : NEGV;
            acc[f][2] = ((mbB >> (2*f)) & 1)   ? acc[f][2]*0.125f : NEGV;
            acc[f][3] = ((mbB >> (2*f+1)) & 1) ? acc[f][3]*0.125f : NEGV;
        }
        float pmA = -3.4e38f, pmB = -3.4e38f;
        #pragma unroll
        for (int f = 0; f < 8; f++) {
            pmA = fmaxf(pmA, fmaxf(acc[f][0], acc[f][1]));
            pmB = fmaxf(pmB, fmaxf(acc[f][2], acc[f][3]));
        }
        pmA = fmaxf(pmA, __shfl_xor_sync(0xffffffffu, pmA, 1));
        pmA = fmaxf(pmA, __shfl_xor_sync(0xffffffffu, pmA, 2));
        pmB = fmaxf(pmB, __shfl_xor_sync(0xffffffffu, pmB, 1));
        pmB = fmaxf(pmB, __shfl_xor_sync(0xffffffffu, pmB, 2));
        if (lq == 0) { stmp[rA*2 + wh] = pmA; stmp[rB*2 + wh] = pmB; }
        __syncthreads();
        float mnA = fmaxf(m_runA, fmaxf(stmp[rA*2], stmp[rA*2+1]));
        float mnB = fmaxf(m_runB, fmaxf(stmp[rB*2], stmp[rB*2+1]));
        float psA = 0.f, psB = 0.f;
        #pragma unroll
        for (int f = 0; f < 8; f++) {
            psA += __expf(acc[f][0] - mnA) + __expf(acc[f][1] - mnA);
            psB += __expf(acc[f][2] - mnB) + __expf(acc[f][3] - mnB);
        }
        psA += __shfl_xor_sync(0xffffffffu, psA, 1);
        psA += __shfl_xor_sync(0xffffffffu, psA, 2);
        psB += __shfl_xor_sync(0xffffffffu, psB, 1);
        psB += __shfl_xor_sync(0xffffffffu, psB, 2);
        if (lq == 0) { stlp[rA*2 + wh] = psA; stlp[rB*2 + wh] = psB; }
        __syncthreads();
        l_runA = l_runA*__expf(m_runA - mnA) + stlp[rA*2] + stlp[rA*2+1];
        l_runB = l_runB*__expf(m_runB - mnB) + stlp[rB*2] + stlp[rB*2+1];
        m_runA = mnA; m_runB = mnB;
    }
    float mfinA = m_runA, mfinB = m_runB;
    int ufA = (mfinA <= -1.0e8f), ufB = (mfinB <= -1.0e8f);
    float invlA = ufA ? 0.f : 1.f/l_runA;
    float invlB = ufB ? 0.f : 1.f/l_runB;
    if (lq == 0 && wh == 0) { ufr[rA] = ufA; ufr[rB] = ufB; if (ufA | ufB) flg[0] = 1; }
    __syncthreads();
    int anyU = flg[0];

    // ================ pass 2: p + AV ================
    int nproc = anyU ? 16 : nv;
    float accAV[4][4];
    #pragma unroll
    for (int f = 0; f < 4; f++) { accAV[f][0]=0; accAV[f][1]=0; accAV[f][2]=0; accAV[f][3]=0; }
    float* pbase = p + ((size_t)(b*2048 + s*128))*2048;

    for (int idx2 = 0; idx2 < nproc; idx2++) {
        int s2 = anyU ? idx2 : vlist[idx2];
        int bv = (vmask >> s2) & 1;
        __syncthreads();   // previous AV done: P/K reusable
        if (bv) {
            #pragma unroll
            for (int it = 0; it < 2; it++) {
                int idx = tid + (it << 9);
                int r = idx >> 3, c = idx & 7;
                size_t se = ((size_t)((b << 11) + (s2 << 7) + r))*64 + c*8;
                *(uint4*)(smem + OFF_KH + QOFF(r, c)) = *(const uint4*)(g_kh + se);
                *(uint4*)(smem + OFF_KL + QOFF(r, c)) = *(const uint4*)(g_kl + se);
            }
        }
        __syncthreads();
        if (bv) {
            float acc[8][4];
            #pragma unroll
            for (int f = 0; f < 8; f++) { acc[f][0]=0; acc[f][1]=0; acc[f][2]=0; acc[f][3]=0; }
            #pragma unroll
            for (int sp = 0; sp < 3; sp++) {
                uint qb = sb + ((sp == 2) ? OFF_QL : OFF_QH);
                uint kb = sb + ((sp == 1) ? OFF_KL : OFF_KH);
                #pragma unroll
                for (int ks = 0; ks < 4; ks++) {
                    uint4 A = ldsm4(qb + QOFF(aRow, 2*ks + aChS));
                    #pragma unroll
                    for (int fp = 0; fp < 4; fp++) {
                        int n = nb + 16*fp;
                        uint4 Bv = ldsm4(kb + QOFF(n + bRowOff, 2*ks + bChS));
                        mma16816(acc[2*fp],     A, Bv.x, Bv.y);
                        mma16816(acc[2*fp + 1], A, Bv.z, Bv.w);
                    }
                }
            }
            #pragma unroll
            for (int f = 0; f < 8; f++) {
                float e0 = ((mbA >> (2*f)) & 1)   ? __expf(acc[f][0]*0.125f - mfinA) : 0.f;
                float e1 = ((mbA >> (2*f+1)) & 1) ? __expf(acc[f][1]*0.125f - mfinA) : 0.f;
                float e2 = ((mbB >> (2*f)) & 1)   ? __expf(acc[f][2]*0.125f - mfinB) : 0.f;
                float e3 = ((mbB >> (2*f+1)) & 1) ? __expf(acc[f][3]*0.125f - mfinB) : 0.f;
                float p0 = ufA ? P0 : e0*invlA;
                float p1 = ufA ? P0 : e1*invlA;
                float p2 = ufB ? P0 : e2*invlB;
                float p3 = ufB ? P0 : e3*invlB;
                int cw = nb + 8*f + 2*lq;
                *(float2*)(pbase + (size_t)rA*2048 + s2*128 + cw) = make_float2(p0, p1);
                *(float2*)(pbase + (size_t)rB*2048 + s2*128 + cw) = make_float2(p2, p3);
                // P smem bf16 split
                int ch = (wh << 3) + f;
                __nv_bfloat16 h0 = __float2bfloat16(p0), h1 = __float2bfloat16(p1);
                __nv_bfloat16 h2 = __float2bfloat16(p2), h3 = __float2bfloat16(p3);
                __nv_bfloat162 hA(h0, h1), hB(h2, h3);
                __nv_bfloat162 lA(__float2bfloat16(p0 - __bfloat162float(h0)),
                                  __float2bfloat16(p1 - __bfloat162float(h1)));
                __nv_bfloat162 lB(__float2bfloat16(p2 - __bfloat162float(h2)),
                                  __float2bfloat16(p3 - __bfloat162float(h3)));
                *(uint*)(smem + OFF_PH + VOFF(rA, ch) + 4*lq) = *(uint*)&hA;
                *(uint*)(smem + OFF_PL + VOFF(rA, ch) + 4*lq) = *(uint*)&lA;
                *(uint*)(smem + OFF_PH + VOFF(rB, ch) + 4*lq) = *(uint*)&hB;
                *(uint*)(smem + OFF_PL + VOFF(rB, ch) + 4*lq) = *(uint*)&lB;
            }
        } else {
            // invalid block under anyU: P rows = uf ? 1/2048 : 0
            __nv_bfloat16 hp0 = __float2bfloat16(P0);
            __nv_bfloat162 hset(hp0, hp0);
            __nv_bfloat162 zset(__float2bfloat16(0.f), __float2bfloat16(0.f));
            for (int i = tid; i < 2048; i += 512) {
                int r = i >> 4, c = i & 15;
                uint4 hv, zv;
                __nv_bfloat162 vv = ufr[r] ? hset : zset;
                hv.x = hv.y = hv.z = hv.w = *(uint*)&vv;
                zv.x = zv.y = zv.z = zv.w = *(uint*)&zset;
                *(uint4*)(smem + OFF_PH + VOFF(r, c)) = hv;
                *(uint4*)(smem + OFF_PL + VOFF(r, c)) = zv;
            }
            for (int i = tid; i < 4096; i += 512) {
                int r = i >> 5, c4 = i & 31;
                float pv = ufr[r] ? P0 : 0.f;
                *(float4*)(pbase + (size_t)r*2048 + s2*128 + (c4 << 2)) =
                    make_float4(pv, pv, pv, pv);
            }
        }
        // stage V
        #pragma unroll
        for (int it = 0; it < 2; it++) {
            int idx = tid + (it << 9);
            int d = idx >> 4, c = idx & 15;
            size_t se = ((size_t)(b*64 + d))*2048 + s2*128 + c*8;
            *(uint4*)(smem + OFF_VH + VOFF(d, c)) = *(const uint4*)(g_vth + se);
            *(uint4*)(smem + OFF_VL + VOFF(d, c)) = *(const uint4*)(g_vtl + se);
        }
        __syncthreads();
        // AV mma
        #pragma unroll
        for (int sp = 0; sp < 3; sp++) {
            uint pb2 = sb + ((sp == 2) ? OFF_PL : OFF_PH);
            uint vb2 = sb + ((sp == 1) ? OFF_VL : OFF_VH);
            #pragma unroll
            for (int ks = 0; ks < 8; ks++) {
                uint4 A = ldsm4(pb2 + VOFF(aRow, 2*ks + aChS));
                #pragma unroll
                for (int fp = 0; fp < 2; fp++) {
                    int n = db + 16*fp;
                    uint4 Bv = ldsm4(vb2 + VOFF(n + bRowOff, 2*ks + bChS));
                    mma16816(accAV[2*fp],     A, Bv.x, Bv.y);
                    mma16816(accAV[2*fp + 1], A, Bv.z, Bv.w);
                }
            }
        }
    }

    // zero-fill p for skipped invalid blocks
    if (!anyU) {
        for (int s2 = 0; s2 < 16; s2++) {
            if ((vmask >> s2) & 1) continue;
            float4 z = make_float4(0.f, 0.f, 0.f, 0.f);
            for (int i = tid; i < 4096; i += 512) {
                int r = i >> 5, c4 = i & 31;
                *(float4*)(pbase + (size_t)r*2048 + s2*128 + (c4 << 2)) = z;
            }
        }
    }

    // ctx out
    {
        float* cb = ctx + ((size_t)(b*2048 + s*128))*64;
        #pragma unroll
        for (int f = 0; f < 4; f++) {
            int dc = db + 8*f + 2*lq;
            *(float2*)(cb + (size_t)rA*64 + dc) = make_float2(accAV[f][0], accAV[f][1]);
            *(float2*)(cb + (size_t)rB*64 + dc) = make_float2(accAV[f][2], accAV[f][3]);
        }
    }
}

#define SMEM1 ((64*68 + 3*64*68 + 3*64) * 4)

extern "C" void kernel_launch(void* const* d_in, const int* in_sizes, int n_in,
                              void* d_out, int out_size) {
    const float* x    = (const float*)d_in[0];
    const int*   tags = (const int*)  d_in[1];
    const float* mk   = (const float*)d_in[2];
    const float* Wk_w = (const float*)d_in[3];
    const float* Wk_b = (const float*)d_in[4];
    const float* Wq_w = (const float*)d_in[5];
    const float* Wq_b = (const float*)d_in[6];
    const float* Wv_w = (const float*)d_in[7];
    const float* Wv_b = (const float*)d_in[8];

    float* ctx = (float*)d_out;                        // [8,16,128,64]
    float* p   = ctx + (size_t)BB*SS*TT*DD;            // [8,2048,2048]

    cudaFuncSetAttribute(qkv_kernel,  cudaFuncAttributeMaxDynamicSharedMemorySize, SMEM1);
    cudaFuncSetAttribute(attn_kernel, cudaFuncAttributeMaxDynamicSharedMemorySize, SMEM_AT);

    qkv_kernel<<<256, 256, SMEM1>>>(x, Wq_w, Wq_b, Wk_w, Wk_b, Wv_w, Wv_b);
    attn_kernel<<<dim3(SS, BB), 512, SMEM_AT>>>(tags, mk, ctx, p);
}

// round 10
// speedup vs baseline: 3.3165x; 1.2252x over previous
#include <cuda_runtime.h>
#include <cuda_bf16.h>

#define BB 8
#define SS 16
#define TT 128
#define DD 64
#define NN 2048
#define NEGV (-1000000000.0f)
#define P0  (0.00048828125f)   // 1/2048

typedef unsigned long long ull;
typedef unsigned int uint;

// bf16 split operands
__device__ __nv_bfloat16 g_qh[BB*NN*DD], g_ql[BB*NN*DD];
__device__ __nv_bfloat16 g_kh[BB*NN*DD], g_kl[BB*NN*DD];
__device__ __nv_bfloat16 g_vph[BB*NN*DD], g_vpl[BB*NN*DD]; // [b][m][d], m = t*16+s

__device__ __forceinline__ ull pk2(float x, float y){
    ull r; asm("mov.b64 %0, {%1, %2};" : "=l"(r) : "f"(x), "f"(y)); return r;
}
__device__ __forceinline__ void fma2(ull &d, ull a, ull b){
    asm("fma.rn.f32x2 %0, %1, %2, %0;" : "+l"(d) : "l"(a), "l"(b));
}
__device__ __forceinline__ float2 upk2(ull v){
    float2 r; asm("mov.b64 {%0, %1}, %2;" : "=f"(r.x), "=f"(r.y) : "l"(v)); return r;
}

// ---------------- kernel 1: QKV projection -> bf16 splits ----------------
__global__ void __launch_bounds__(256)
qkv_kernel(const float* __restrict__ x,
           const float* __restrict__ Wq_w, const float* __restrict__ Wq_b,
           const float* __restrict__ Wk_w, const float* __restrict__ Wk_b,
           const float* __restrict__ Wv_w, const float* __restrict__ Wv_b)
{
    extern __shared__ float sm1[];
    float* xs = sm1;               // [64][68]
    float* wt = xs + 64*68;        // [3][64][68]
    float* bs = wt + 3*64*68;      // [3][64]

    int tid = threadIdx.x;
    int r0  = blockIdx.x * 64;

    for (int idx = tid; idx < 64*64; idx += 256) {
        int c = idx >> 6, kk = idx & 63;
        wt[(0*64 + kk)*68 + c] = Wq_w[idx];
        wt[(1*64 + kk)*68 + c] = Wk_w[idx];
        wt[(2*64 + kk)*68 + c] = Wv_w[idx];
    }
    if (tid < 64) {
        bs[tid]       = Wq_b[tid];
        bs[64 + tid]  = Wk_b[tid];
        bs[128 + tid] = Wv_b[tid];
    }
    #pragma unroll
    for (int it = 0; it < 4; it++) {
        int idx = tid + (it << 8);
        int r = idx >> 4, f = idx & 15;
        float4 v = *(const float4*)(x + (size_t)(r0 + r)*64 + (f << 2));
        *(float4*)&xs[r*68 + (f << 2)] = v;
    }
    __syncthreads();

    int cg   = tid & 7;
    int rg   = tid >> 3;
    int row0 = rg << 1;
    const float* x0p = &xs[row0 * 68];
    const float* x1p = x0p + 68;
    int gr0 = r0 + row0;
    int b_  = gr0 >> 11;

    for (int mat = 0; mat < 3; mat++) {
        ull a0[4], a1[4];
        {
            const ulonglong2* bp = (const ulonglong2*)(bs + mat*64 + 8*cg);
            ulonglong2 b01 = bp[0], b23 = bp[1];
            a0[0]=b01.x; a0[1]=b01.y; a0[2]=b23.x; a0[3]=b23.y;
            a1[0]=b01.x; a1[1]=b01.y; a1[2]=b23.x; a1[3]=b23.y;
        }
        const float* wp = &wt[mat*64*68 + 8*cg];
        #pragma unroll 4
        for (int kk = 0; kk < 64; kk++) {
            float q0 = x0p[kk], q1 = x1p[kk];
            ull q0p = pk2(q0, q0), q1p = pk2(q1, q1);
            ulonglong2 w01 = *(const ulonglong2*)(wp + kk*68);
            ulonglong2 w23 = *(const ulonglong2*)(wp + kk*68 + 4);
            fma2(a0[0], q0p, w01.x); fma2(a0[1], q0p, w01.y);
            fma2(a0[2], q0p, w23.x); fma2(a0[3], q0p, w23.y);
            fma2(a1[0], q1p, w01.x); fma2(a1[1], q1p, w01.y);
            fma2(a1[2], q1p, w23.x); fma2(a1[3], q1p, w23.y);
        }
        #pragma unroll
        for (int rr = 0; rr < 2; rr++) {
            int gr = gr0 + rr;
            ull* ap = rr ? a1 : a0;
            float f[8];
            { float2 u0=upk2(ap[0]),u1=upk2(ap[1]),u2=upk2(ap[2]),u3=upk2(ap[3]);
              f[0]=u0.x; f[1]=u0.y; f[2]=u1.x; f[3]=u1.y;
              f[4]=u2.x; f[5]=u2.y; f[6]=u3.x; f[7]=u3.y; }
            __nv_bfloat16 h[8]; __nv_bfloat16 lo[8];
            #pragma unroll
            for (int i = 0; i < 8; i++) {
                h[i]  = __float2bfloat16(f[i]);
                lo[i] = __float2bfloat16(f[i] - __bfloat162float(h[i]));
            }
            if (mat < 2) {
                __nv_bfloat16* dh = (mat == 0) ? g_qh : g_kh;
                __nv_bfloat16* dl = (mat == 0) ? g_ql : g_kl;
                *(uint4*)(dh + (size_t)gr*64 + 8*cg) = *(uint4*)h;
                *(uint4*)(dl + (size_t)gr*64 + 8*cg) = *(uint4*)lo;
            } else {
                int n = gr & 2047;
                int s_ = n >> 7, t_ = n & 127;
                int m  = t_*16 + s_;
                *(uint4*)(g_vph + ((size_t)(b_ << 11) + m)*64 + 8*cg) = *(uint4*)h;
                *(uint4*)(g_vpl + ((size_t)(b_ << 11) + m)*64 + 8*cg) = *(uint4*)lo;
            }
        }
    }
}

// ---------------- attention (mma.sync bf16-split, no-max softmax) ----------------
#define OFF_QH 0
#define OFF_QL 16384
#define OFF_KH 32768
#define OFF_KL 49152
#define OFF_VH 65536
#define OFF_VL 81920
#define OFF_PH 98304
#define OFF_PL 131072
#define OFF_MSB  163840
#define OFF_STLP 166912
#define OFF_UF   167936
#define OFF_FLAG 168448
#define OFF_TAGS 168452
#define SMEM_AT  168576

#define QOFF(r,c) ((uint)((r)*128 + (((c) ^ ((r)&7)) << 4)))
#define VOFF(r,c) ((uint)((r)*256 + (((c) ^ ((r)&7)) << 4)))

__device__ __forceinline__ uint smem_u32(const void* p){
    uint a; asm("{ .reg .u64 t; cvta.to.shared.u64 t, %1; cvt.u32.u64 %0, t; }" : "=r"(a) : "l"(p));
    return a;
}
__device__ __forceinline__ uint4 ldsm4(uint addr){
    uint4 r;
    asm volatile("ldmatrix.sync.aligned.m8n8.x4.shared.b16 {%0,%1,%2,%3}, [%4];"
        : "=r"(r.x), "=r"(r.y), "=r"(r.z), "=r"(r.w) : "r"(addr));
    return r;
}
__device__ __forceinline__ uint4 ldsm4t(uint addr){
    uint4 r;
    asm volatile("ldmatrix.sync.aligned.m8n8.x4.trans.shared.b16 {%0,%1,%2,%3}, [%4];"
        : "=r"(r.x), "=r"(r.y), "=r"(r.z), "=r"(r.w) : "r"(addr));
    return r;
}
__device__ __forceinline__ void mma16816(float* d, uint4 a, uint b0, uint b1){
    asm volatile("mma.sync.aligned.m16n8k16.row.col.f32.bf16.bf16.f32 "
        "{%0,%1,%2,%3}, {%4,%5,%6,%7}, {%8,%9}, {%0,%1,%2,%3};"
        : "+f"(d[0]), "+f"(d[1]), "+f"(d[2]), "+f"(d[3])
        : "r"(a.x), "r"(a.y), "r"(a.z), "r"(a.w), "r"(b0), "r"(b1));
}

__global__ void __launch_bounds__(512, 1)
attn_kernel(const int* __restrict__ tags, const float* __restrict__ mask,
            float* __restrict__ ctx, float* __restrict__ p)
{
    extern __shared__ char smem[];
    uint sb = smem_u32(smem);
    int tid  = threadIdx.x;
    int wid  = tid >> 5, lane = tid & 31;
    int wr   = wid >> 1;
    int wh   = wid & 1;
    int m0   = wr << 4;
    int nb   = wh << 6;
    int db   = wh << 5;
    int s    = blockIdx.x;
    int b    = blockIdx.y;
    int lq   = lane & 3;
    int lr   = lane >> 2;
    int rA   = m0 + lr, rB = rA + 8;

    int*   tgs  = (int*)(smem + OFF_TAGS);
    uint*  msb  = (uint*)(smem + OFF_MSB);
    float* stlp = (float*)(smem + OFF_STLP);
    int*   ufr  = (int*)(smem + OFF_UF);
    int*   flg  = (int*)(smem + OFF_FLAG);

    if (tid < 16) tgs[tid] = tags[b*16 + tid];
    if (tid == 0) flg[0] = 0;
    for (int i = tid; i < 512; i += 512) {
        int tt = i >> 2, w = i & 3;
        uint bits = 0;
        #pragma unroll 8
        for (int j = 0; j < 32; j++)
            bits |= (mask[(size_t)tt*128 + w*32 + j] != 0.f ? 1u : 0u) << j;
        msb[i] = bits;
    }
    // stage Q
    #pragma unroll
    for (int it = 0; it < 2; it++) {
        int idx = tid + (it << 9);
        int r = idx >> 3, c = idx & 7;
        size_t se = ((size_t)((b << 11) + (s << 7) + r))*64 + c*8;
        *(uint4*)(smem + OFF_QH + QOFF(r, c)) = *(const uint4*)(g_qh + se);
        *(uint4*)(smem + OFF_QL + QOFF(r, c)) = *(const uint4*)(g_ql + se);
    }
    __syncthreads();

    int mytag = tgs[s];
    uint vmask = 0;
    #pragma unroll
    for (int s2 = 0; s2 < 16; s2++) if (tgs[s2] == mytag) vmask |= 1u << s2;
    int vlist[16], nv = 0;
    #pragma unroll
    for (int s2 = 0; s2 < 16; s2++) if ((vmask >> s2) & 1) vlist[nv++] = s2;

    uint mbA = 0, mbB = 0;
    #pragma unroll
    for (int f = 0; f < 8; f++)
        #pragma unroll
        for (int u = 0; u < 2; u++) {
            int cw = nb + 8*f + 2*lq + u;
            mbA |= ((msb[rA*4 + (cw >> 5)] >> (cw & 31)) & 1u) << (f*2 + u);
            mbB |= ((msb[rB*4 + (cw >> 5)] >> (cw & 31)) & 1u) << (f*2 + u);
        }

    int aRow = m0 + (lane & 7) + ((lane >> 3) & 1)*8;
    int aChS = (lane >> 4);
    int bRowOff = (lane & 7) + ((lane >= 16) ? 8 : 0);
    int bChS = ((lane >> 3) & 1);
    int vRowOff = (lane & 7) + (((lane >> 3) & 1) << 3);   // trans B (V)
    int vChS = (lane >> 4);

    // ================ pass 1: l = sum exp(s), hi-only QK, dbl-buffered K ===========
    float lsA = 0.f, lsB = 0.f;
    {
        // stage block 0 (hi) into KH
        #pragma unroll
        for (int it = 0; it < 2; it++) {
            int idx = tid + (it << 9);
            int r = idx >> 3, c = idx & 7;
            size_t se = ((size_t)((b << 11) + (vlist[0] << 7) + r))*64 + c*8;
            *(uint4*)(smem + OFF_KH + QOFF(r, c)) = *(const uint4*)(g_kh + se);
        }
        __syncthreads();
        for (int vi = 0; vi < nv; vi++) {
            if (vi + 1 < nv) {
                uint dsto = ((vi + 1) & 1) ? OFF_KL : OFF_KH;
                #pragma unroll
                for (int it = 0; it < 2; it++) {
                    int idx = tid + (it << 9);
                    int r = idx >> 3, c = idx & 7;
                    size_t se = ((size_t)((b << 11) + (vlist[vi+1] << 7) + r))*64 + c*8;
                    *(uint4*)(smem + dsto + QOFF(r, c)) = *(const uint4*)(g_kh + se);
                }
            }
            uint kb = sb + ((vi & 1) ? OFF_KL : OFF_KH);
            float acc[8][4];
            #pragma unroll
            for (int f = 0; f < 8; f++) { acc[f][0]=0; acc[f][1]=0; acc[f][2]=0; acc[f][3]=0; }
            uint qb = sb + OFF_QH;
            #pragma unroll
            for (int ks = 0; ks < 4; ks++) {
                uint4 A = ldsm4(qb + QOFF(aRow, 2*ks + aChS));
                #pragma unroll
                for (int fp = 0; fp < 4; fp++) {
                    int n = nb + 16*fp;
                    uint4 Bv = ldsm4(kb + QOFF(n + bRowOff, 2*ks + bChS));
                    mma16816(acc[2*fp],     A, Bv.x, Bv.y);
                    mma16816(acc[2*fp + 1], A, Bv.z, Bv.w);
                }
            }
            #pragma unroll
            for (int f = 0; f < 8; f++) {
                lsA += (((mbA >> (2*f)) & 1)   ? __expf(acc[f][0]*0.125f) : 0.f)
                     + (((mbA >> (2*f+1)) & 1) ? __expf(acc[f][1]*0.125f) : 0.f);
                lsB += (((mbB >> (2*f)) & 1)   ? __expf(acc[f][2]*0.125f) : 0.f)
                     + (((mbB >> (2*f+1)) & 1) ? __expf(acc[f][3]*0.125f) : 0.f);
            }
            __syncthreads();
        }
    }
    lsA += __shfl_xor_sync(0xffffffffu, lsA, 1);
    lsA += __shfl_xor_sync(0xffffffffu, lsA, 2);
    lsB += __shfl_xor_sync(0xffffffffu, lsB, 1);
    lsB += __shfl_xor_sync(0xffffffffu, lsB, 2);
    if (lq == 0) { stlp[rA*2 + wh] = lsA; stlp[rB*2 + wh] = lsB; }
    __syncthreads();
    float lA = stlp[rA*2] + stlp[rA*2+1];
    float lB = stlp[rB*2] + stlp[rB*2+1];
    int ufA = (lA == 0.f), ufB = (lB == 0.f);
    float invlA = ufA ? 0.f : 1.f/lA;
    float invlB = ufB ? 0.f : 1.f/lB;
    if (lq == 0 && wh == 0) { ufr[rA] = ufA; ufr[rB] = ufB; if (ufA | ufB) flg[0] = 1; }
    __syncthreads();
    int anyU = flg[0];

    // ================ pass 2: p + AV ================
    int nproc = anyU ? 16 : nv;
    float accAV[4][4];
    #pragma unroll
    for (int f = 0; f < 4; f++) { accAV[f][0]=0; accAV[f][1]=0; accAV[f][2]=0; accAV[f][3]=0; }
    float* pbase = p + ((size_t)(b*2048 + s*128))*2048;

    for (int idx2 = 0; idx2 < nproc; idx2++) {
        int s2 = anyU ? idx2 : vlist[idx2];
        int bv = (vmask >> s2) & 1;
        __syncthreads();   // previous AV ldsm reads done before restaging
        if (bv) {
            #pragma unroll
            for (int it = 0; it < 2; it++) {
                int idx = tid + (it << 9);
                int r = idx >> 3, c = idx & 7;
                size_t se = ((size_t)((b << 11) + (s2 << 7) + r))*64 + c*8;
                *(uint4*)(smem + OFF_KH + QOFF(r, c)) = *(const uint4*)(g_kh + se);
                *(uint4*)(smem + OFF_KL + QOFF(r, c)) = *(const uint4*)(g_kl + se);
            }
        }
        // stage V from [m][d] layout (coalesced)
        #pragma unroll
        for (int it = 0; it < 2; it++) {
            int idx = tid + (it << 9);
            int r = idx >> 3, c = idx & 7;
            size_t se = ((size_t)((b << 11) + (s2 << 7) + r))*64 + c*8;
            *(uint4*)(smem + OFF_VH + QOFF(r, c)) = *(const uint4*)(g_vph + se);
            *(uint4*)(smem + OFF_VL + QOFF(r, c)) = *(const uint4*)(g_vpl + se);
        }
        __syncthreads();
        if (bv) {
            float acc[8][4];
            #pragma unroll
            for (int f = 0; f < 8; f++) { acc[f][0]=0; acc[f][1]=0; acc[f][2]=0; acc[f][3]=0; }
            #pragma unroll
            for (int sp = 0; sp < 3; sp++) {
                uint qb = sb + ((sp == 2) ? OFF_QL : OFF_QH);
                uint kb = sb + ((sp == 1) ? OFF_KL : OFF_KH);
                #pragma unroll
                for (int ks = 0; ks < 4; ks++) {
                    uint4 A = ldsm4(qb + QOFF(aRow, 2*ks + aChS));
                    #pragma unroll
                    for (int fp = 0; fp < 4; fp++) {
                        int n = nb + 16*fp;
                        uint4 Bv = ldsm4(kb + QOFF(n + bRowOff, 2*ks + bChS));
                        mma16816(acc[2*fp],     A, Bv.x, Bv.y);
                        mma16816(acc[2*fp + 1], A, Bv.z, Bv.w);
                    }
                }
            }
            #pragma unroll
            for (int f = 0; f < 8; f++) {
                float e0 = ((mbA >> (2*f)) & 1)   ? __expf(acc[f][0]*0.125f) : 0.f;
                float e1 = ((mbA >> (2*f+1)) & 1) ? __expf(acc[f][1]*0.125f) : 0.f;
                float e2 = ((mbB >> (2*f)) & 1)   ? __expf(acc[f][2]*0.125f) : 0.f;
                float e3 = ((mbB >> (2*f+1)) & 1) ? __expf(acc[f][3]*0.125f) : 0.f;
                float p0 = ufA ? P0 : e0*invlA;
                float p1 = ufA ? P0 : e1*invlA;
                float p2 = ufB ? P0 : e2*invlB;
                float p3 = ufB ? P0 : e3*invlB;
                int cw = nb + 8*f + 2*lq;
                *(float2*)(pbase + (size_t)rA*2048 + s2*128 + cw) = make_float2(p0, p1);
                *(float2*)(pbase + (size_t)rB*2048 + s2*128 + cw) = make_float2(p2, p3);
                int ch = (wh << 3) + f;
                __nv_bfloat16 h0 = __float2bfloat16(p0), h1 = __float2bfloat16(p1);
                __nv_bfloat16 h2 = __float2bfloat16(p2), h3 = __float2bfloat16(p3);
                __nv_bfloat162 hA(h0, h1), hB(h2, h3);
                __nv_bfloat162 lA2(__float2bfloat16(p0 - __bfloat162float(h0)),
                                   __float2bfloat16(p1 - __bfloat162float(h1)));
                __nv_bfloat162 lB2(__float2bfloat16(p2 - __bfloat162float(h2)),
                                   __float2bfloat16(p3 - __bfloat162float(h3)));
                *(uint*)(smem + OFF_PH + VOFF(rA, ch) + 4*lq) = *(uint*)&hA;
                *(uint*)(smem + OFF_PL + VOFF(rA, ch) + 4*lq) = *(uint*)&lA2;
                *(uint*)(smem + OFF_PH + VOFF(rB, ch) + 4*lq) = *(uint*)&hB;
                *(uint*)(smem + OFF_PL + VOFF(rB, ch) + 4*lq) = *(uint*)&lB2;
            }
        } else {
            __nv_bfloat16 hp0 = __float2bfloat16(P0);
            __nv_bfloat162 hset(hp0, hp0);
            __nv_bfloat162 zset(__float2bfloat16(0.f), __float2bfloat16(0.f));
            for (int i = tid; i < 2048; i += 512) {
                int r = i >> 4, c = i & 15;
                uint4 hv, zv;
                __nv_bfloat162 vv = ufr[r] ? hset : zset;
                hv.x = hv.y = hv.z = hv.w = *(uint*)&vv;
                zv.x = zv.y = zv.z = zv.w = *(uint*)&zset;
                *(uint4*)(smem + OFF_PH + VOFF(r, c)) = hv;
                *(uint4*)(smem + OFF_PL + VOFF(r, c)) = zv;
            }
            for (int i = tid; i < 4096; i += 512) {
                int r = i >> 5, c4 = i & 31;
                float pv = ufr[r] ? P0 : 0.f;
                *(float4*)(pbase + (size_t)r*2048 + s2*128 + (c4 << 2)) =
                    make_float4(pv, pv, pv, pv);
            }
        }
        __syncthreads();
        // AV mma: B = V from [m][d] storage via ldmatrix.trans
        #pragma unroll
        for (int sp = 0; sp < 3; sp++) {
            uint pb2 = sb + ((sp == 2) ? OFF_PL : OFF_PH);
            uint vb2 = sb + ((sp == 1) ? OFF_VL : OFF_VH);
            #pragma unroll
            for (int ks = 0; ks < 8; ks++) {
                uint4 A = ldsm4(pb2 + VOFF(aRow, 2*ks + aChS));
                #pragma unroll
                for (int fp = 0; fp < 2; fp++) {
                    int cch = ((db + 16*fp) >> 3) + vChS;
                    uint4 Bv = ldsm4t(vb2 + QOFF(16*ks + vRowOff, cch));
                    mma16816(accAV[2*fp],     A, Bv.x, Bv.y);
                    mma16816(accAV[2*fp + 1], A, Bv.z, Bv.w);
                }
            }
        }
    }

    if (!anyU) {
        for (int s2 = 0; s2 < 16; s2++) {
            if ((vmask >> s2) & 1) continue;
            float4 z = make_float4(0.f, 0.f, 0.f, 0.f);
            for (int i = tid; i < 4096; i += 512) {
                int r = i >> 5, c4 = i & 31;
                *(float4*)(pbase + (size_t)r*2048 + s2*128 + (c4 << 2)) = z;
            }
        }
    }

    {
        float* cb = ctx + ((size_t)(b*2048 + s*128))*64;
        #pragma unroll
        for (int f = 0; f < 4; f++) {
            int dc = db + 8*f + 2*lq;
            *(float2*)(cb + (size_t)rA*64 + dc) = make_float2(accAV[f][0], accAV[f][1]);
            *(float2*)(cb + (size_t)rB*64 + dc) = make_float2(accAV[f][2], accAV[f][3]);
        }
    }
}

#define SMEM1 ((64*68 + 3*64*68 + 3*64) * 4)

extern "C" void kernel_launch(void* const* d_in, const int* in_sizes, int n_in,
                              void* d_out, int out_size) {
    const float* x    = (const float*)d_in[0];
    const int*   tags = (const int*)  d_in[1];
    const float* mk   = (const float*)d_in[2];
    const float* Wk_w = (const float*)d_in[3];
    const float* Wk_b = (const float*)d_in[4];
    const float* Wq_w = (const float*)d_in[5];
    const float* Wq_b = (const float*)d_in[6];
    const float* Wv_w = (const float*)d_in[7];
    const float* Wv_b = (const float*)d_in[8];

    float* ctx = (float*)d_out;                        // [8,16,128,64]
    float* p   = ctx + (size_t)BB*SS*TT*DD;            // [8,2048,2048]

    cudaFuncSetAttribute(qkv_kernel,  cudaFuncAttributeMaxDynamicSharedMemorySize, SMEM1);
    cudaFuncSetAttribute(attn_kernel, cudaFuncAttributeMaxDynamicSharedMemorySize, SMEM_AT);

    qkv_kernel<<<256, 256, SMEM1>>>(x, Wq_w, Wq_b, Wk_w, Wk_b, Wv_w, Wv_b);
    attn_kernel<<<dim3(SS, BB), 512, SMEM_AT>>>(tags, mk, ctx, p);
}

// round 11
// speedup vs baseline: 3.9859x; 1.2018x over previous
#include <cuda_runtime.h>
#include <cuda_bf16.h>

#define BB 8
#define SS 16
#define TT 128
#define DD 64
#define NN 2048
#define P0  (0.00048828125f)   // 1/2048

typedef unsigned long long ull;
typedef unsigned int uint;

// bf16 split operands
__device__ __nv_bfloat16 g_qh[BB*NN*DD], g_ql[BB*NN*DD];
__device__ __nv_bfloat16 g_kh[BB*NN*DD], g_kl[BB*NN*DD];
__device__ __nv_bfloat16 g_vph[BB*NN*DD], g_vpl[BB*NN*DD]; // [b][m][d], m = t*16+s

__device__ __forceinline__ ull pk2(float x, float y){
    ull r; asm("mov.b64 %0, {%1, %2};" : "=l"(r) : "f"(x), "f"(y)); return r;
}
__device__ __forceinline__ void fma2(ull &d, ull a, ull b){
    asm("fma.rn.f32x2 %0, %1, %2, %0;" : "+l"(d) : "l"(a), "l"(b));
}
__device__ __forceinline__ float2 upk2(ull v){
    float2 r; asm("mov.b64 {%0, %1}, %2;" : "=f"(r.x), "=f"(r.y) : "l"(v)); return r;
}

// ---------------- kernel 1: QKV projection -> bf16 splits (1 wave) ----------------
__global__ void __launch_bounds__(512)
qkv_kernel(const float* __restrict__ x,
           const float* __restrict__ Wq_w, const float* __restrict__ Wq_b,
           const float* __restrict__ Wk_w, const float* __restrict__ Wk_b,
           const float* __restrict__ Wv_w, const float* __restrict__ Wv_b)
{
    extern __shared__ float sm1[];
    float* xs = sm1;               // [128][68]
    float* wt = xs + 128*68;       // [3][64][68]
    float* bs = wt + 3*64*68;      // [3][64]

    int tid = threadIdx.x;
    int r0  = blockIdx.x * 128;

    for (int idx = tid; idx < 64*64; idx += 512) {
        int c = idx >> 6, kk = idx & 63;
        wt[(0*64 + kk)*68 + c] = Wq_w[idx];
        wt[(1*64 + kk)*68 + c] = Wk_w[idx];
        wt[(2*64 + kk)*68 + c] = Wv_w[idx];
    }
    if (tid < 64) {
        bs[tid]       = Wq_b[tid];
        bs[64 + tid]  = Wk_b[tid];
        bs[128 + tid] = Wv_b[tid];
    }
    #pragma unroll
    for (int it = 0; it < 4; it++) {
        int idx = tid + (it << 9);
        int r = idx >> 4, f = idx & 15;
        float4 v = *(const float4*)(x + (size_t)(r0 + r)*64 + (f << 2));
        *(float4*)&xs[r*68 + (f << 2)] = v;
    }
    __syncthreads();

    int cg   = tid & 7;
    int rg   = tid >> 3;          // 0..63
    int row0 = rg << 1;
    const float* x0p = &xs[row0 * 68];
    const float* x1p = x0p + 68;
    int gr0 = r0 + row0;
    int b_  = gr0 >> 11;

    for (int mat = 0; mat < 3; mat++) {
        ull a0[4], a1[4];
        {
            const ulonglong2* bp = (const ulonglong2*)(bs + mat*64 + 8*cg);
            ulonglong2 b01 = bp[0], b23 = bp[1];
            a0[0]=b01.x; a0[1]=b01.y; a0[2]=b23.x; a0[3]=b23.y;
            a1[0]=b01.x; a1[1]=b01.y; a1[2]=b23.x; a1[3]=b23.y;
        }
        const float* wp = &wt[mat*64*68 + 8*cg];
        #pragma unroll 4
        for (int kk = 0; kk < 64; kk++) {
            float q0 = x0p[kk], q1 = x1p[kk];
            ull q0p = pk2(q0, q0), q1p = pk2(q1, q1);
            ulonglong2 w01 = *(const ulonglong2*)(wp + kk*68);
            ulonglong2 w23 = *(const ulonglong2*)(wp + kk*68 + 4);
            fma2(a0[0], q0p, w01.x); fma2(a0[1], q0p, w01.y);
            fma2(a0[2], q0p, w23.x); fma2(a0[3], q0p, w23.y);
            fma2(a1[0], q1p, w01.x); fma2(a1[1], q1p, w01.y);
            fma2(a1[2], q1p, w23.x); fma2(a1[3], q1p, w23.y);
        }
        #pragma unroll
        for (int rr = 0; rr < 2; rr++) {
            int gr = gr0 + rr;
            ull* ap = rr ? a1 : a0;
            float f[8];
            { float2 u0=upk2(ap[0]),u1=upk2(ap[1]),u2=upk2(ap[2]),u3=upk2(ap[3]);
              f[0]=u0.x; f[1]=u0.y; f[2]=u1.x; f[3]=u1.y;
              f[4]=u2.x; f[5]=u2.y; f[6]=u3.x; f[7]=u3.y; }
            __nv_bfloat16 h[8]; __nv_bfloat16 lo[8];
            #pragma unroll
            for (int i = 0; i < 8; i++) {
                h[i]  = __float2bfloat16(f[i]);
                lo[i] = __float2bfloat16(f[i] - __bfloat162float(h[i]));
            }
            if (mat < 2) {
                __nv_bfloat16* dh = (mat == 0) ? g_qh : g_kh;
                __nv_bfloat16* dl = (mat == 0) ? g_ql : g_kl;
                *(uint4*)(dh + (size_t)gr*64 + 8*cg) = *(uint4*)h;
                *(uint4*)(dl + (size_t)gr*64 + 8*cg) = *(uint4*)lo;
            } else {
                int n = gr & 2047;
                int s_ = n >> 7, t_ = n & 127;
                int m  = t_*16 + s_;
                *(uint4*)(g_vph + ((size_t)(b_ << 11) + m)*64 + 8*cg) = *(uint4*)h;
                *(uint4*)(g_vpl + ((size_t)(b_ << 11) + m)*64 + 8*cg) = *(uint4*)lo;
            }
        }
    }
}

// ---------------- attention ----------------
#define OFF_QH 0
#define OFF_QL 16384
#define OFF_K0 32768
#define OFF_K0L 49152
#define OFF_K1 65536
#define OFF_K1L 81920
#define OFF_VH 98304
#define OFF_VL 114688
#define OFF_PH 131072
#define OFF_PL 163840
#define OFF_MSB  196608
#define OFF_STLP 198656
#define OFF_UF   199680
#define OFF_FLAG 200192
#define OFF_TAGS 200196
#define SMEM_AT  200448

#define QOFF(r,c) ((uint)((r)*128 + (((c) ^ ((r)&7)) << 4)))
#define VOFF(r,c) ((uint)((r)*256 + (((c) ^ ((r)&7)) << 4)))

__device__ __forceinline__ uint smem_u32(const void* p){
    uint a; asm("{ .reg .u64 t; cvta.to.shared.u64 t, %1; cvt.u32.u64 %0, t; }" : "=r"(a) : "l"(p));
    return a;
}
__device__ __forceinline__ void cpa16(uint dst, const void* src){
    asm volatile("cp.async.cg.shared.global [%0], [%1], 16;"
        :: "r"(dst), "l"(__cvta_generic_to_global(src)) : "memory");
}
#define CPA_COMMIT() asm volatile("cp.async.commit_group;" ::: "memory")
#define CPA_WAIT0()  asm volatile("cp.async.wait_group 0;" ::: "memory")
#define CPA_WAIT1()  asm volatile("cp.async.wait_group 1;" ::: "memory")

__device__ __forceinline__ uint4 ldsm4(uint addr){
    uint4 r;
    asm volatile("ldmatrix.sync.aligned.m8n8.x4.shared.b16 {%0,%1,%2,%3}, [%4];"
        : "=r"(r.x), "=r"(r.y), "=r"(r.z), "=r"(r.w) : "r"(addr));
    return r;
}
__device__ __forceinline__ uint4 ldsm4t(uint addr){
    uint4 r;
    asm volatile("ldmatrix.sync.aligned.m8n8.x4.trans.shared.b16 {%0,%1,%2,%3}, [%4];"
        : "=r"(r.x), "=r"(r.y), "=r"(r.z), "=r"(r.w) : "r"(addr));
    return r;
}
__device__ __forceinline__ void mma16816(float* d, uint4 a, uint b0, uint b1){
    asm volatile("mma.sync.aligned.m16n8k16.row.col.f32.bf16.bf16.f32 "
        "{%0,%1,%2,%3}, {%4,%5,%6,%7}, {%8,%9}, {%0,%1,%2,%3};"
        : "+f"(d[0]), "+f"(d[1]), "+f"(d[2]), "+f"(d[3])
        : "r"(a.x), "r"(a.y), "r"(a.z), "r"(a.w), "r"(b0), "r"(b1));
}

__global__ void __launch_bounds__(512, 1)
attn_kernel(const int* __restrict__ tags, const float* __restrict__ mask,
            float* __restrict__ ctx, float* __restrict__ p)
{
    extern __shared__ char smem[];
    uint sb = smem_u32(smem);
    int tid  = threadIdx.x;
    int wid  = tid >> 5, lane = tid & 31;
    int wr   = wid >> 1;
    int wh   = wid & 1;
    int m0   = wr << 4;
    int nb   = wh << 6;
    int db   = wh << 5;
    int s    = blockIdx.x;
    int b    = blockIdx.y;
    int lq   = lane & 3;
    int lr   = lane >> 2;
    int rA   = m0 + lr, rB = rA + 8;

    int*   tgs  = (int*)(smem + OFF_TAGS);
    uint*  msb  = (uint*)(smem + OFF_MSB);
    float* stlp = (float*)(smem + OFF_STLP);
    int*   ufr  = (int*)(smem + OFF_UF);
    int*   flg  = (int*)(smem + OFF_FLAG);

    if (tid < 16) tgs[tid] = tags[b*16 + tid];
    if (tid == 0) flg[0] = 0;
    for (int i = tid; i < 512; i += 512) {
        int tt = i >> 2, w = i & 3;
        uint bits = 0;
        #pragma unroll 8
        for (int j = 0; j < 32; j++)
            bits |= (mask[(size_t)tt*128 + w*32 + j] != 0.f ? 1u : 0u) << j;
        msb[i] = bits;
    }
    // stage Q (cp.async)
    #pragma unroll
    for (int it = 0; it < 2; it++) {
        int idx = tid + (it << 9);
        int r = idx >> 3, c = idx & 7;
        size_t se = ((size_t)((b << 11) + (s << 7) + r))*64 + c*8;
        cpa16(sb + OFF_QH + QOFF(r, c), g_qh + se);
        cpa16(sb + OFF_QL + QOFF(r, c), g_ql + se);
    }
    CPA_COMMIT();
    __syncthreads();

    int mytag = tgs[s];
    uint vmask = 0;
    #pragma unroll
    for (int s2 = 0; s2 < 16; s2++) if (tgs[s2] == mytag) vmask |= 1u << s2;
    int vlist[16], nv = 0;
    #pragma unroll
    for (int s2 = 0; s2 < 16; s2++) if ((vmask >> s2) & 1) vlist[nv++] = s2;

    uint mbA = 0, mbB = 0;
    #pragma unroll
    for (int f = 0; f < 8; f++)
        #pragma unroll
        for (int u = 0; u < 2; u++) {
            int cw = nb + 8*f + 2*lq + u;
            mbA |= ((msb[rA*4 + (cw >> 5)] >> (cw & 31)) & 1u) << (f*2 + u);
            mbB |= ((msb[rB*4 + (cw >> 5)] >> (cw & 31)) & 1u) << (f*2 + u);
        }

    int aRow = m0 + (lane & 7) + ((lane >> 3) & 1)*8;
    int aChS = (lane >> 4);
    int bRowOff = (lane & 7) + ((lane >= 16) ? 8 : 0);
    int bChS = ((lane >> 3) & 1);
    int vRowOff = (lane & 7) + (((lane >> 3) & 1) << 3);
    int vChS = (lane >> 4);

    const __nv_bfloat16* gb_kh = g_kh + ((size_t)b << 17);
    const __nv_bfloat16* gb_kl = g_kl + ((size_t)b << 17);
    const __nv_bfloat16* gb_vh = g_vph + ((size_t)b << 17);
    const __nv_bfloat16* gb_vl = g_vpl + ((size_t)b << 17);

    // ================ pass 1: l = sum exp(s), (qh+ql)*kh, cp.async dbl-buffer ======
    float lsA = 0.f, lsB = 0.f;
    {
        // prologue: K(0) hi -> buf0
        #pragma unroll
        for (int it = 0; it < 2; it++) {
            int idx = tid + (it << 9);
            int r = idx >> 3, c = idx & 7;
            cpa16(sb + OFF_K0 + QOFF(r, c), gb_kh + ((size_t)((vlist[0] << 7) + r))*64 + c*8);
        }
        CPA_COMMIT();
        for (int vi = 0; vi < nv; vi++) {
            CPA_WAIT0();
            __syncthreads();
            if (vi + 1 < nv) {
                uint dsto = ((vi + 1) & 1) ? OFF_K1 : OFF_K0;
                #pragma unroll
                for (int it = 0; it < 2; it++) {
                    int idx = tid + (it << 9);
                    int r = idx >> 3, c = idx & 7;
                    cpa16(sb + dsto + QOFF(r, c), gb_kh + ((size_t)((vlist[vi+1] << 7) + r))*64 + c*8);
                }
                CPA_COMMIT();
            }
            uint kb = sb + ((vi & 1) ? OFF_K1 : OFF_K0);
            float acc[8][4];
            #pragma unroll
            for (int f = 0; f < 8; f++) { acc[f][0]=0; acc[f][1]=0; acc[f][2]=0; acc[f][3]=0; }
            #pragma unroll
            for (int ks = 0; ks < 4; ks++) {
                uint4 Ah = ldsm4(sb + OFF_QH + QOFF(aRow, 2*ks + aChS));
                uint4 Al = ldsm4(sb + OFF_QL + QOFF(aRow, 2*ks + aChS));
                #pragma unroll
                for (int fp = 0; fp < 4; fp++) {
                    int n = nb + 16*fp;
                    uint4 Bv = ldsm4(kb + QOFF(n + bRowOff, 2*ks + bChS));
                    mma16816(acc[2*fp],     Ah, Bv.x, Bv.y);
                    mma16816(acc[2*fp + 1], Ah, Bv.z, Bv.w);
                    mma16816(acc[2*fp],     Al, Bv.x, Bv.y);
                    mma16816(acc[2*fp + 1], Al, Bv.z, Bv.w);
                }
            }
            #pragma unroll
            for (int f = 0; f < 8; f++) {
                lsA += (((mbA >> (2*f)) & 1)   ? __expf(acc[f][0]*0.125f) : 0.f)
                     + (((mbA >> (2*f+1)) & 1) ? __expf(acc[f][1]*0.125f) : 0.f);
                lsB += (((mbB >> (2*f)) & 1)   ? __expf(acc[f][2]*0.125f) : 0.f)
                     + (((mbB >> (2*f+1)) & 1) ? __expf(acc[f][3]*0.125f) : 0.f);
            }
        }
    }
    lsA += __shfl_xor_sync(0xffffffffu, lsA, 1);
    lsA += __shfl_xor_sync(0xffffffffu, lsA, 2);
    lsB += __shfl_xor_sync(0xffffffffu, lsB, 1);
    lsB += __shfl_xor_sync(0xffffffffu, lsB, 2);
    __syncthreads();
    if (lq == 0) { stlp[rA*2 + wh] = lsA; stlp[rB*2 + wh] = lsB; }
    __syncthreads();
    float lA = stlp[rA*2] + stlp[rA*2+1];
    float lB = stlp[rB*2] + stlp[rB*2+1];
    int ufA = (lA == 0.f), ufB = (lB == 0.f);
    float invlA = ufA ? 0.f : 1.f/lA;
    float invlB = ufB ? 0.f : 1.f/lB;
    if (lq == 0 && wh == 0) { ufr[rA] = ufA; ufr[rB] = ufB; if (ufA | ufB) flg[0] = 1; }
    __syncthreads();
    int anyU = flg[0];

    // ================ pass 2: p + AV ================
    int nproc = anyU ? 16 : nv;
    float accAV[4][4];
    #pragma unroll
    for (int f = 0; f < 4; f++) { accAV[f][0]=0; accAV[f][1]=0; accAV[f][2]=0; accAV[f][3]=0; }
    float* pbase = p + ((size_t)(b*2048 + s*128))*2048;

    // prologue: K(0) hi+lo -> buf0
    {
        int blk0 = anyU ? 0 : vlist[0];
        #pragma unroll
        for (int it = 0; it < 2; it++) {
            int idx = tid + (it << 9);
            int r = idx >> 3, c = idx & 7;
            size_t se = ((size_t)((blk0 << 7) + r))*64 + c*8;
            cpa16(sb + OFF_K0  + QOFF(r, c), gb_kh + se);
            cpa16(sb + OFF_K0L + QOFF(r, c), gb_kl + se);
        }
        CPA_COMMIT();
    }

    for (int idx2 = 0; idx2 < nproc; idx2++) {
        int s2 = anyU ? idx2 : vlist[idx2];
        int bv = (vmask >> s2) & 1;
        CPA_WAIT0();
        __syncthreads();   // K(idx2) ready; all prior AV reads done
        // issue V(idx2) (committed first), then K(idx2+1)
        #pragma unroll
        for (int it = 0; it < 2; it++) {
            int idx = tid + (it << 9);
            int r = idx >> 3, c = idx & 7;
            size_t se = ((size_t)((s2 << 7) + r))*64 + c*8;
            cpa16(sb + OFF_VH + QOFF(r, c), gb_vh + se);
            cpa16(sb + OFF_VL + QOFF(r, c), gb_vl + se);
        }
        CPA_COMMIT();
        int havenext = (idx2 + 1 < nproc);
        if (havenext) {
            int s3 = anyU ? (idx2 + 1) : vlist[idx2 + 1];
            uint dh = ((idx2 + 1) & 1) ? OFF_K1 : OFF_K0;
            uint dl = ((idx2 + 1) & 1) ? OFF_K1L : OFF_K0L;
            #pragma unroll
            for (int it = 0; it < 2; it++) {
                int idx = tid + (it << 9);
                int r = idx >> 3, c = idx & 7;
                size_t se = ((size_t)((s3 << 7) + r))*64 + c*8;
                cpa16(sb + dh + QOFF(r, c), gb_kh + se);
                cpa16(sb + dl + QOFF(r, c), gb_kl + se);
            }
            CPA_COMMIT();
        }
        uint kbh = sb + ((idx2 & 1) ? OFF_K1 : OFF_K0);
        uint kbl = sb + ((idx2 & 1) ? OFF_K1L : OFF_K0L);
        if (bv) {
            float acc[8][4];
            #pragma unroll
            for (int f = 0; f < 8; f++) { acc[f][0]=0; acc[f][1]=0; acc[f][2]=0; acc[f][3]=0; }
            #pragma unroll
            for (int ks = 0; ks < 4; ks++) {
                uint4 Ah = ldsm4(sb + OFF_QH + QOFF(aRow, 2*ks + aChS));
                uint4 Al = ldsm4(sb + OFF_QL + QOFF(aRow, 2*ks + aChS));
                #pragma unroll
                for (int fp = 0; fp < 4; fp++) {
                    int n = nb + 16*fp;
                    uint4 Bh = ldsm4(kbh + QOFF(n + bRowOff, 2*ks + bChS));
                    mma16816(acc[2*fp],     Ah, Bh.x, Bh.y);
                    mma16816(acc[2*fp + 1], Ah, Bh.z, Bh.w);
                    mma16816(acc[2*fp],     Al, Bh.x, Bh.y);
                    mma16816(acc[2*fp + 1], Al, Bh.z, Bh.w);
                    uint4 Bl = ldsm4(kbl + QOFF(n + bRowOff, 2*ks + bChS));
                    mma16816(acc[2*fp],     Ah, Bl.x, Bl.y);
                    mma16816(acc[2*fp + 1], Ah, Bl.z, Bl.w);
                }
            }
            #pragma unroll
            for (int f = 0; f < 8; f++) {
                float e0 = ((mbA >> (2*f)) & 1)   ? __expf(acc[f][0]*0.125f) : 0.f;
                float e1 = ((mbA >> (2*f+1)) & 1) ? __expf(acc[f][1]*0.125f) : 0.f;
                float e2 = ((mbB >> (2*f)) & 1)   ? __expf(acc[f][2]*0.125f) : 0.f;
                float e3 = ((mbB >> (2*f+1)) & 1) ? __expf(acc[f][3]*0.125f) : 0.f;
                float p0 = ufA ? P0 : e0*invlA;
                float p1 = ufA ? P0 : e1*invlA;
                float p2 = ufB ? P0 : e2*invlB;
                float p3 = ufB ? P0 : e3*invlB;
                int cw = nb + 8*f + 2*lq;
                *(float2*)(pbase + (size_t)rA*2048 + s2*128 + cw) = make_float2(p0, p1);
                *(float2*)(pbase + (size_t)rB*2048 + s2*128 + cw) = make_float2(p2, p3);
                int ch = (wh << 3) + f;
                __nv_bfloat16 h0 = __float2bfloat16(p0), h1 = __float2bfloat16(p1);
                __nv_bfloat16 h2 = __float2bfloat16(p2), h3 = __float2bfloat16(p3);
                __nv_bfloat162 hA(h0, h1), hB(h2, h3);
                __nv_bfloat162 lA2(__float2bfloat16(p0 - __bfloat162float(h0)),
                                   __float2bfloat16(p1 - __bfloat162float(h1)));
                __nv_bfloat162 lB2(__float2bfloat16(p2 - __bfloat162float(h2)),
                                   __float2bfloat16(p3 - __bfloat162float(h3)));
                *(uint*)(smem + OFF_PH + VOFF(rA, ch) + 4*lq) = *(uint*)&hA;
                *(uint*)(smem + OFF_PL + VOFF(rA, ch) + 4*lq) = *(uint*)&lA2;
                *(uint*)(smem + OFF_PH + VOFF(rB, ch) + 4*lq) = *(uint*)&hB;
                *(uint*)(smem + OFF_PL + VOFF(rB, ch) + 4*lq) = *(uint*)&lB2;
            }
        } else {
            __nv_bfloat16 hp0 = __float2bfloat16(P0);
            __nv_bfloat162 hset(hp0, hp0);
            __nv_bfloat162 zset(__float2bfloat16(0.f), __float2bfloat16(0.f));
            for (int i = tid; i < 2048; i += 512) {
                int r = i >> 4, c = i & 15;
                uint4 hv, zv;
                __nv_bfloat162 vv = ufr[r] ? hset : zset;
                hv.x = hv.y = hv.z = hv.w = *(uint*)&vv;
                zv.x = zv.y = zv.z = zv.w = *(uint*)&zset;
                *(uint4*)(smem + OFF_PH + VOFF(r, c)) = hv;
                *(uint4*)(smem + OFF_PL + VOFF(r, c)) = zv;
            }
            for (int i = tid; i < 4096; i += 512) {
                int r = i >> 5, c4 = i & 31;
                float pv = ufr[r] ? P0 : 0.f;
                *(float4*)(pbase + (size_t)r*2048 + s2*128 + (c4 << 2)) =
                    make_float4(pv, pv, pv, pv);
            }
        }
        if (havenext) { CPA_WAIT1(); } else { CPA_WAIT0(); }   // V(idx2) ready
        __syncthreads();                                        // P + V visible
        #pragma unroll
        for (int ks = 0; ks < 8; ks++) {
            uint4 Ah = ldsm4(sb + OFF_PH + VOFF(aRow, 2*ks + aChS));
            uint4 Al = ldsm4(sb + OFF_PL + VOFF(aRow, 2*ks + aChS));
            #pragma unroll
            for (int fp = 0; fp < 2; fp++) {
                int cch = ((db + 16*fp) >> 3) + vChS;
                uint4 Bh = ldsm4t(sb + OFF_VH + QOFF(16*ks + vRowOff, cch));
                mma16816(accAV[2*fp],     Ah, Bh.x, Bh.y);
                mma16816(accAV[2*fp + 1], Ah, Bh.z, Bh.w);
                mma16816(accAV[2*fp],     Al, Bh.x, Bh.y);
                mma16816(accAV[2*fp + 1], Al, Bh.z, Bh.w);
                uint4 Bl = ldsm4t(sb + OFF_VL + QOFF(16*ks + vRowOff, cch));
                mma16816(accAV[2*fp],     Ah, Bl.x, Bl.y);
                mma16816(accAV[2*fp + 1], Ah, Bl.z, Bl.w);
            }
        }
    }

    if (!anyU) {
        for (int s2 = 0; s2 < 16; s2++) {
            if ((vmask >> s2) & 1) continue;
            float4 z = make_float4(0.f, 0.f, 0.f, 0.f);
            for (int i = tid; i < 4096; i += 512) {
                int r = i >> 5, c4 = i & 31;
                *(float4*)(pbase + (size_t)r*2048 + s2*128 + (c4 << 2)) = z;
            }
        }
    }

    {
        float* cb = ctx + ((size_t)(b*2048 + s*128))*64;
        #pragma unroll
        for (int f = 0; f < 4; f++) {
            int dc = db + 8*f + 2*lq;
            *(float2*)(cb + (size_t)rA*64 + dc) = make_float2(accAV[f][0], accAV[f][1]);
            *(float2*)(cb + (size_t)rB*64 + dc) = make_float2(accAV[f][2], accAV[f][3]);
        }
    }
}

#define SMEM1 ((128*68 + 3*64*68 + 3*64) * 4)

extern "C" void kernel_launch(void* const* d_in, const int* in_sizes, int n_in,
                              void* d_out, int out_size) {
    const float* x    = (const float*)d_in[0];
    const int*   tags = (const int*)  d_in[1];
    const float* mk   = (const float*)d_in[2];
    const float* Wk_w = (const float*)d_in[3];
    const float* Wk_b = (const float*)d_in[4];
    const float* Wq_w = (const float*)d_in[5];
    const float* Wq_b = (const float*)d_in[6];
    const float* Wv_w = (const float*)d_in[7];
    const float* Wv_b = (const float*)d_in[8];

    float* ctx = (float*)d_out;                        // [8,16,128,64]
    float* p   = ctx + (size_t)BB*SS*TT*DD;            // [8,2048,2048]

    cudaFuncSetAttribute(qkv_kernel,  cudaFuncAttributeMaxDynamicSharedMemorySize, SMEM1);
    cudaFuncSetAttribute(attn_kernel, cudaFuncAttributeMaxDynamicSharedMemorySize, SMEM_AT);

    qkv_kernel<<<128, 512, SMEM1>>>(x, Wq_w, Wq_b, Wk_w, Wk_b, Wv_w, Wv_b);
    attn_kernel<<<dim3(SS, BB), 512, SMEM_AT>>>(tags, mk, ctx, p);
}